// round 8
// baseline (speedup 1.0000x reference)
#include <cuda_runtime.h>
#include <math.h>
#include <stdint.h>

#define LAYERS 8
#define HDIM   1024
#define KDIM   1024
#define IDIM   4096
#define VOCAB  32000
#define BATCH  2
#define SEQ    2048
#define MTOK   (BATCH * SEQ)

// ---------------- fp32 scratch ----------------
__device__ float g_x[(long)MTOK * HDIM];
__device__ float g_qkv[(long)MTOK * 3 * KDIM];
__device__ float g_scores[(long)BATCH * SEQ * SEQ];
__device__ float g_o[(long)MTOK * KDIM];
__device__ float g_h[(long)MTOK * IDIM];
__device__ float g_vT[(long)BATCH * KDIM * SEQ];
__device__ float g_wsc[(long)LAYERS * IDIM * HDIM];   // transpose scratch (reused)

// ---------------- int8 quantized operands ----------------
__device__ int8_t g_xq1[(long)MTOK * HDIM],  g_xq2[(long)MTOK * HDIM];
__device__ float  g_xs[MTOK];
__device__ int8_t g_qq1[(long)MTOK * KDIM],  g_qq2[(long)MTOK * KDIM];
__device__ float  g_qs[MTOK];
__device__ int8_t g_kq1[(long)MTOK * KDIM],  g_kq2[(long)MTOK * KDIM];
__device__ float  g_ks[MTOK];
__device__ int8_t g_pq1[(long)BATCH * SEQ * SEQ], g_pq2[(long)BATCH * SEQ * SEQ];
__device__ float  g_ps[(long)BATCH * SEQ];
__device__ int8_t g_vq1[(long)BATCH * KDIM * SEQ], g_vq2[(long)BATCH * KDIM * SEQ];
__device__ float  g_vs[(long)BATCH * KDIM];
__device__ int8_t g_oq1[(long)MTOK * KDIM],  g_oq2[(long)MTOK * KDIM];
__device__ float  g_os[MTOK];
__device__ int8_t g_hq1[(long)MTOK * IDIM],  g_hq2[(long)MTOK * IDIM];
__device__ float  g_hs[MTOK];
// weights [N,K] quantized
__device__ int8_t g_wqkv1[(long)LAYERS * 3 * KDIM * HDIM], g_wqkv2[(long)LAYERS * 3 * KDIM * HDIM];
__device__ float  g_sqkv[(long)LAYERS * 3 * KDIM];
__device__ int8_t g_wo1[(long)LAYERS * HDIM * KDIM], g_wo2[(long)LAYERS * HDIM * KDIM];
__device__ float  g_so[(long)LAYERS * HDIM];
__device__ int8_t g_wu1[(long)LAYERS * IDIM * HDIM], g_wu2[(long)LAYERS * IDIM * HDIM];
__device__ float  g_su[(long)LAYERS * IDIM];
__device__ int8_t g_wd1[(long)LAYERS * HDIM * IDIM], g_wd2[(long)LAYERS * HDIM * IDIM];
__device__ float  g_sd[(long)LAYERS * HDIM];
__device__ int8_t g_wun1[(long)VOCAB * HDIM], g_wun2[(long)VOCAB * HDIM];
__device__ float  g_sun[VOCAB];

// ---------------- helpers ----------------
__device__ __forceinline__ uint32_t smem_u32(const void* p) {
    uint32_t a;
    asm("{ .reg .u64 t; cvta.to.shared.u64 t, %1; cvt.u32.u64 %0, t; }" : "=r"(a) : "l"(p));
    return a;
}
#define CP_ASYNC16(dst, src) \
    asm volatile("cp.async.cg.shared.global [%0], [%1], 16;" :: "r"(dst), "l"(src) : "memory")
#define CP_COMMIT() asm volatile("cp.async.commit_group;" ::: "memory")
#define CP_WAIT1()  asm volatile("cp.async.wait_group 1;" ::: "memory")
#define LDSM_X4(r, a)                                                        \
    asm volatile("ldmatrix.sync.aligned.m8n8.x4.shared.b16 {%0,%1,%2,%3}, [%4];" \
        : "=r"((r)[0]), "=r"((r)[1]), "=r"((r)[2]), "=r"((r)[3]) : "r"(a))

__device__ __forceinline__ void mma_s8(int* c, const uint32_t* a, uint32_t b0, uint32_t b1) {
    asm volatile(
        "mma.sync.aligned.m16n8k32.row.col.s32.s8.s8.s32 "
        "{%0,%1,%2,%3}, {%4,%5,%6,%7}, {%8,%9}, {%0,%1,%2,%3};"
        : "+r"(c[0]), "+r"(c[1]), "+r"(c[2]), "+r"(c[3])
        : "r"(a[0]), "r"(a[1]), "r"(a[2]), "r"(a[3]), "r"(b0), "r"(b1));
}

__device__ __forceinline__ void quant2(float v, float inv, int8_t& a, int8_t& b) {
    float t = v * inv;                       // in [-127,127]
    int q1 = __float2int_rn(t);
    int q2 = __float2int_rn((t - (float)q1) * 254.f);
    a = (int8_t)q1; b = (int8_t)q2;
}

// ---------------- embed + quant ----------------
__global__ void embed_quant(const int* __restrict__ tokens, const float* __restrict__ emb,
                            float* __restrict__ x,
                            int8_t* __restrict__ q1, int8_t* __restrict__ q2,
                            float* __restrict__ s) {
    __shared__ float buf[HDIM];
    __shared__ float red[256];
    int i = blockIdx.x;
    const float* src = emb + (long)tokens[i] * HDIM;
    int tid = threadIdx.x;
    float m = 0.f;
    for (int c = tid; c < HDIM; c += 256) {
        float v = src[c];
        buf[c] = v;
        x[(long)i * HDIM + c] = v;
        m = fmaxf(m, fabsf(v));
    }
    red[tid] = m; __syncthreads();
    for (int o = 128; o > 0; o >>= 1) { if (tid < o) red[tid] = fmaxf(red[tid], red[tid + o]); __syncthreads(); }
    float rmax = red[0];
    float inv = (rmax > 0.f) ? 127.f / rmax : 0.f;
    if (tid == 0) s[i] = (rmax > 0.f) ? rmax / 127.f : 0.f;
    for (int c = tid; c < HDIM; c += 256) {
        int8_t a, b; quant2(buf[c], inv, a, b);
        q1[(long)i * HDIM + c] = a; q2[(long)i * HDIM + c] = b;
    }
}

// ---------------- row quantize (strided input, dense output) ----------------
__global__ void rowquant(const float* __restrict__ src, int ld, int K,
                         int8_t* __restrict__ q1, int8_t* __restrict__ q2,
                         float* __restrict__ s) {
    extern __shared__ float buf[];
    __shared__ float red[256];
    long row = blockIdx.x;
    src += row * ld;
    q1 += row * K; q2 += row * K;
    int tid = threadIdx.x;
    float m = 0.f;
    for (int c = tid; c < K; c += 256) { float v = src[c]; buf[c] = v; m = fmaxf(m, fabsf(v)); }
    red[tid] = m; __syncthreads();
    for (int o = 128; o > 0; o >>= 1) { if (tid < o) red[tid] = fmaxf(red[tid], red[tid + o]); __syncthreads(); }
    float rmax = red[0];
    float inv = (rmax > 0.f) ? 127.f / rmax : 0.f;
    if (tid == 0) s[row] = (rmax > 0.f) ? rmax / 127.f : 0.f;
    for (int c = tid; c < K; c += 256) {
        int8_t a, b; quant2(buf[c], inv, a, b);
        q1[c] = a; q2[c] = b;
    }
}

// ---------------- fp32 transpose ----------------
__global__ void transpose_f32(const float* __restrict__ src, float* __restrict__ dst,
                              int R, int lds, long sbatch, long dbatch) {
    __shared__ float t[32][33];
    src += (long)blockIdx.z * sbatch;
    dst += (long)blockIdx.z * dbatch;
    int c0 = blockIdx.x << 5, r0 = blockIdx.y << 5;
    int x = threadIdx.x, y = threadIdx.y;
    #pragma unroll
    for (int i = y; i < 32; i += 8)
        t[i][x] = src[(long)(r0 + i) * lds + c0 + x];
    __syncthreads();
    #pragma unroll
    for (int j = y; j < 32; j += 8)
        dst[(long)(c0 + j) * R + r0 + x] = t[x][j];
}

// ---------------- causal softmax -> int8 quant ----------------
__global__ void softmax_quant(const float* __restrict__ sc,
                              int8_t* __restrict__ q1, int8_t* __restrict__ q2,
                              float* __restrict__ qs, float scale) {
    __shared__ float red[256];
    extern __shared__ float e[];             // SEQ floats
    int row = blockIdx.x;
    int s = row & (SEQ - 1);
    const float* p = sc + (long)row * SEQ;
    int8_t* p1 = q1 + (long)row * SEQ;
    int8_t* p2 = q2 + (long)row * SEQ;
    int tid = threadIdx.x;

    float m = -INFINITY;
    for (int t = tid; t <= s; t += 256) m = fmaxf(m, p[t] * scale);
    red[tid] = m; __syncthreads();
    for (int o = 128; o > 0; o >>= 1) { if (tid < o) red[tid] = fmaxf(red[tid], red[tid + o]); __syncthreads(); }
    m = red[0]; __syncthreads();

    float sum = 0.f;
    for (int t = tid; t <= s; t += 256) {
        float v = __expf(p[t] * scale - m);
        e[t] = v;
        sum += v;
    }
    red[tid] = sum; __syncthreads();
    for (int o = 128; o > 0; o >>= 1) { if (tid < o) red[tid] += red[tid + o]; __syncthreads(); }
    float inv = 1.f / red[0];
    if (tid == 0) qs[row] = inv / 127.f;     // prob = s*(q1 + q2/254), s = inv/127
    for (int t = tid; t <= s; t += 256) {
        float t127 = 127.f * e[t];           // prob/s = 127*e
        int a = __float2int_rn(t127);
        int b = __float2int_rn((t127 - (float)a) * 254.f);
        p1[t] = (int8_t)a; p2[t] = (int8_t)b;
    }
    for (int t = s + 1 + tid; t < SEQ; t += 256) { p1[t] = 0; p2[t] = 0; }
}

// ---------------- INT8 IMMA GEMM: C[M,N] = A[M,K] @ B[N,K]^T ----------------
// CTA 128x128x32, 256 thr, 8 warps (2Mx4N), 64x32 warp tiles.
// A = sa*(A1 + A2/254), B analog; 3 mmas: P11 -> acc1, P12+P21 -> acc2.
// EPI: 0 store, 1 +=C, 2 relu(+bias), 3 +bias+C, 4 +bias
#define DEPTH     3
#define ROWP      48u                    // int8 row pitch in smem
#define COMP_B    (128u * ROWP)          // 6144
#define STG_BYTES (4u * COMP_B)          // 24576
#define SMEM_TOT  (DEPTH * STG_BYTES)    // 73728

template<int EPI, bool CSKIP, bool CK>
__global__ __launch_bounds__(256, 1)
void imma_gemm(const int8_t* __restrict__ A1, const int8_t* __restrict__ A2,
               const float* __restrict__ Sa,
               const int8_t* __restrict__ B1, const int8_t* __restrict__ B2,
               const float* __restrict__ Sb,
               float* __restrict__ C, const float* __restrict__ bias,
               int K, int lda, int ldb, int ldc,
               long bsA, long bsB, long bsC, long bsSa, long bsSb) {
    const int m0 = blockIdx.y << 7, n0 = blockIdx.x << 7;
    if (CSKIP && n0 > m0 + 127) return;
    const long zA = (long)blockIdx.z * bsA;
    const long zB = (long)blockIdx.z * bsB;
    const long zC = (long)blockIdx.z * bsC;
    Sa += (long)blockIdx.z * bsSa + m0;
    Sb += (long)blockIdx.z * bsSb + n0;

    extern __shared__ char smem[];
    const uint32_t sbase = smem_u32(smem);
    const int tid = threadIdx.x;
    const int lane = tid & 31, wid = tid >> 5;
    const int wm = wid & 1, wn = wid >> 1;
    int NK = K >> 5;
    if (CK) { int nke = (m0 + 128) >> 5; NK = (nke < NK) ? nke : NK; }

    const int8_t* gm[4] = { A1 + zA + (long)m0 * lda, A2 + zA + (long)m0 * lda,
                            B1 + zB + (long)n0 * ldb, B2 + zB + (long)n0 * ldb };
    const int ldm[4] = { lda, lda, ldb, ldb };
    const int row = tid >> 1;
    const uint32_t chunk = (uint32_t)(tid & 1) << 4;

    int acc1[4][4][4], acc2[4][4][4];
    #pragma unroll
    for (int a = 0; a < 4; a++)
        #pragma unroll
        for (int b = 0; b < 4; b++)
            #pragma unroll
            for (int c = 0; c < 4; c++) { acc1[a][b][c] = 0; acc2[a][b][c] = 0; }

    #define LOAD_STAGE(kt, slot) do {                                           \
        uint32_t st_ = sbase + (slot) * STG_BYTES;                              \
        _Pragma("unroll")                                                       \
        for (int cmp = 0; cmp < 4; cmp++) {                                     \
            const int8_t* g = gm[cmp] + (long)row * ldm[cmp] + ((kt) << 5) + chunk; \
            CP_ASYNC16(st_ + cmp * COMP_B + (uint32_t)row * ROWP + chunk, g);   \
        }                                                                       \
        CP_COMMIT();                                                            \
    } while (0)

    LOAD_STAGE(0, 0);
    LOAD_STAGE(1, 1);

    for (int kt = 0; kt < NK; kt++) {
        CP_WAIT1();
        __syncthreads();
        if (kt + 2 < NK) { LOAD_STAGE(kt + 2, (kt + 2) % DEPTH); }
        else             { CP_COMMIT(); }

        uint32_t st = sbase + (kt % DEPTH) * STG_BYTES;
        uint32_t a1[4][4], a2[4][4];
        #pragma unroll
        for (int mt = 0; mt < 4; mt++) {
            uint32_t ad = st + (uint32_t)(wm * 64 + mt * 16 + (lane & 15)) * ROWP
                          + ((lane >> 4) << 4);
            LDSM_X4(a1[mt], ad);
            LDSM_X4(a2[mt], ad + COMP_B);
        }
        #pragma unroll
        for (int p = 0; p < 2; p++) {
            uint32_t b1[4], b2[4];
            uint32_t bd = st + 2u * COMP_B
                          + (uint32_t)(wn * 32 + p * 16 + ((lane >> 4) << 3) + (lane & 7)) * ROWP
                          + (((lane >> 3) & 1) << 4);
            LDSM_X4(b1, bd);
            LDSM_X4(b2, bd + COMP_B);
            #pragma unroll
            for (int q = 0; q < 2; q++) {
                const int nt = p * 2 + q;
                uint32_t x0 = b1[q * 2], x1 = b1[q * 2 + 1];
                uint32_t y0 = b2[q * 2], y1 = b2[q * 2 + 1];
                #pragma unroll
                for (int mt = 0; mt < 4; mt++) {
                    mma_s8(acc1[mt][nt], a1[mt], x0, x1);
                    mma_s8(acc2[mt][nt], a1[mt], y0, y1);
                    mma_s8(acc2[mt][nt], a2[mt], x0, x1);
                }
            }
        }
    }

    // ---- epilogue: C = sa*sb*(acc1 + acc2/254) (+ bias/residual/relu) ----
    const float r254 = 1.f / 254.f;
    #pragma unroll
    for (int mt = 0; mt < 4; mt++) {
        #pragma unroll
        for (int hf = 0; hf < 2; hf++) {
            const int mi = wm * 64 + mt * 16 + (lane >> 2) + hf * 8;
            const float sam = Sa[mi];
            const long mrow = zC + (long)(m0 + mi) * ldc;
            #pragma unroll
            for (int nt = 0; nt < 4; nt++) {
                const int ni = wn * 32 + nt * 8 + (lane & 3) * 2;
                float vx = sam * Sb[ni] *
                           ((float)acc1[mt][nt][hf * 2 + 0] + (float)acc2[mt][nt][hf * 2 + 0] * r254);
                float vy = sam * Sb[ni + 1] *
                           ((float)acc1[mt][nt][hf * 2 + 1] + (float)acc2[mt][nt][hf * 2 + 1] * r254);
                long idx = mrow + n0 + ni;
                if (EPI >= 2) { vx += bias[n0 + ni]; vy += bias[n0 + ni + 1]; }
                if (EPI == 2) { vx = fmaxf(vx, 0.f); vy = fmaxf(vy, 0.f); }
                if (EPI == 1 || EPI == 3) {
                    float2 old = *(const float2*)(C + idx);
                    vx += old.x; vy += old.y;
                }
                float2 o; o.x = vx; o.y = vy;
                *(float2*)(C + idx) = o;
            }
        }
    }
}

// ---------------- host ----------------
template<int EPI, bool CSKIP = false, bool CK = false>
static void launch_imma(dim3 grid,
                        const int8_t* A1, const int8_t* A2, const float* Sa,
                        const int8_t* B1, const int8_t* B2, const float* Sb,
                        float* C, const float* bias, int K, int lda, int ldb, int ldc,
                        long bsA = 0, long bsB = 0, long bsC = 0,
                        long bsSa = 0, long bsSb = 0) {
    cudaFuncSetAttribute(imma_gemm<EPI, CSKIP, CK>,
                         cudaFuncAttributeMaxDynamicSharedMemorySize, SMEM_TOT);
    imma_gemm<EPI, CSKIP, CK><<<grid, 256, SMEM_TOT>>>(
        A1, A2, Sa, B1, B2, Sb, C, bias, K, lda, ldb, ldc, bsA, bsB, bsC, bsSa, bsSb);
}

#define SYM(p, g) cudaGetSymbolAddress((void**)&p, g)

extern "C" void kernel_launch(void* const* d_in, const int* in_sizes, int n_in,
                              void* d_out, int out_size) {
    const int*   tokens    = (const int*)  d_in[0];
    const float* embedding = (const float*)d_in[1];
    const float* qkv_w     = (const float*)d_in[2];
    const float* o_w       = (const float*)d_in[3];
    const float* up_w      = (const float*)d_in[4];
    const float* up_b      = (const float*)d_in[5];
    const float* down_w    = (const float*)d_in[6];
    const float* down_b    = (const float*)d_in[7];
    const float* unemb_w   = (const float*)d_in[8];
    const float* unemb_b   = (const float*)d_in[9];
    float* logits = (float*)d_out;

    float *x, *qkv, *sc, *o, *h, *vT, *wsc;
    SYM(x, g_x); SYM(qkv, g_qkv); SYM(sc, g_scores); SYM(o, g_o); SYM(h, g_h);
    SYM(vT, g_vT); SYM(wsc, g_wsc);
    int8_t *xq1, *xq2, *qq1, *qq2, *kq1, *kq2, *pq1, *pq2, *vq1, *vq2, *oq1, *oq2, *hq1, *hq2;
    float *xs, *qs, *ks, *ps, *vs, *os, *hs;
    SYM(xq1, g_xq1); SYM(xq2, g_xq2); SYM(xs, g_xs);
    SYM(qq1, g_qq1); SYM(qq2, g_qq2); SYM(qs, g_qs);
    SYM(kq1, g_kq1); SYM(kq2, g_kq2); SYM(ks, g_ks);
    SYM(pq1, g_pq1); SYM(pq2, g_pq2); SYM(ps, g_ps);
    SYM(vq1, g_vq1); SYM(vq2, g_vq2); SYM(vs, g_vs);
    SYM(oq1, g_oq1); SYM(oq2, g_oq2); SYM(os, g_os);
    SYM(hq1, g_hq1); SYM(hq2, g_hq2); SYM(hs, g_hs);
    int8_t *wqkv1, *wqkv2, *wo1, *wo2, *wu1, *wu2, *wd1, *wd2, *wun1, *wun2;
    float *sqkv, *so, *su, *sd, *sun;
    SYM(wqkv1, g_wqkv1); SYM(wqkv2, g_wqkv2); SYM(sqkv, g_sqkv);
    SYM(wo1, g_wo1); SYM(wo2, g_wo2); SYM(so, g_so);
    SYM(wu1, g_wu1); SYM(wu2, g_wu2); SYM(su, g_su);
    SYM(wd1, g_wd1); SYM(wd2, g_wd2); SYM(sd, g_sd);
    SYM(wun1, g_wun1); SYM(wun2, g_wun2); SYM(sun, g_sun);

    const float scale = 1.0f / sqrtf((float)KDIM);
    dim3 tb(32, 8);

    // ---- weight prep: transpose -> [N,K] fp32 scratch -> rowquant ----
    transpose_f32<<<dim3(3 * KDIM / 32, HDIM / 32, LAYERS), tb>>>(
        qkv_w, wsc, HDIM, 3 * KDIM, (long)HDIM * 3 * KDIM, (long)HDIM * 3 * KDIM);
    rowquant<<<LAYERS * 3 * KDIM, 256, HDIM * 4>>>(wsc, HDIM, HDIM, wqkv1, wqkv2, sqkv);

    transpose_f32<<<dim3(HDIM / 32, KDIM / 32, LAYERS), tb>>>(
        o_w, wsc, KDIM, HDIM, (long)KDIM * HDIM, (long)KDIM * HDIM);
    rowquant<<<LAYERS * HDIM, 256, KDIM * 4>>>(wsc, KDIM, KDIM, wo1, wo2, so);

    transpose_f32<<<dim3(IDIM / 32, HDIM / 32, LAYERS), tb>>>(
        up_w, wsc, HDIM, IDIM, (long)HDIM * IDIM, (long)HDIM * IDIM);
    rowquant<<<LAYERS * IDIM, 256, HDIM * 4>>>(wsc, HDIM, HDIM, wu1, wu2, su);

    transpose_f32<<<dim3(HDIM / 32, IDIM / 32, LAYERS), tb>>>(
        down_w, wsc, IDIM, HDIM, (long)IDIM * HDIM, (long)IDIM * HDIM);
    rowquant<<<LAYERS * HDIM, 256, IDIM * 4>>>(wsc, IDIM, IDIM, wd1, wd2, sd);

    transpose_f32<<<dim3(VOCAB / 32, HDIM / 32, 1), tb>>>(unemb_w, wsc, HDIM, VOCAB, 0, 0);
    rowquant<<<VOCAB, 256, HDIM * 4>>>(wsc, HDIM, HDIM, wun1, wun2, sun);

    // ---- embed + quant ----
    embed_quant<<<MTOK, 256>>>(tokens, embedding, x, xq1, xq2, xs);

    for (int l = 0; l < LAYERS; l++) {
        const int8_t* wq1 = wqkv1 + (long)l * 3 * KDIM * HDIM;
        const int8_t* wq2 = wqkv2 + (long)l * 3 * KDIM * HDIM;
        const float*  wqs = sqkv  + (long)l * 3 * KDIM;
        const int8_t* wo1l = wo1 + (long)l * HDIM * KDIM;
        const int8_t* wo2l = wo2 + (long)l * HDIM * KDIM;
        const float*  wosl = so  + (long)l * HDIM;
        const int8_t* wu1l = wu1 + (long)l * IDIM * HDIM;
        const int8_t* wu2l = wu2 + (long)l * IDIM * HDIM;
        const float*  wusl = su  + (long)l * IDIM;
        const int8_t* wd1l = wd1 + (long)l * HDIM * IDIM;
        const int8_t* wd2l = wd2 + (long)l * HDIM * IDIM;
        const float*  wdsl = sd  + (long)l * HDIM;
        const float* bu = up_b   + (long)l * IDIM;
        const float* bd = down_b + (long)l * HDIM;

        // qkv = x @ Wqkv^T
        launch_imma<0>(dim3(3 * KDIM / 128, MTOK / 128, 1),
            xq1, xq2, xs, wq1, wq2, wqs, qkv, nullptr,
            HDIM, HDIM, HDIM, 3 * KDIM);

        // quant Q, K (strided rows of qkv)
        rowquant<<<MTOK, 256, KDIM * 4>>>(qkv,            3 * KDIM, KDIM, qq1, qq2, qs);
        rowquant<<<MTOK, 256, KDIM * 4>>>(qkv + KDIM,     3 * KDIM, KDIM, kq1, kq2, ks);

        // V^T fp32, then quant rows (kdim rows of length SEQ)
        transpose_f32<<<dim3(KDIM / 32, SEQ / 32, BATCH), tb>>>(
            qkv + 2 * KDIM, vT, SEQ, 3 * KDIM, (long)SEQ * 3 * KDIM, (long)KDIM * SEQ);
        rowquant<<<BATCH * KDIM, 256, SEQ * 4>>>(vT, SEQ, SEQ, vq1, vq2, vs);

        // scores = Q @ K^T (causal block skip)
        launch_imma<0, true, false>(dim3(SEQ / 128, SEQ / 128, BATCH),
            qq1, qq2, qs, kq1, kq2, ks, sc, nullptr,
            KDIM, KDIM, KDIM, SEQ,
            (long)SEQ * KDIM, (long)SEQ * KDIM, (long)SEQ * SEQ, SEQ, SEQ);

        softmax_quant<<<BATCH * SEQ, 256, SEQ * 4>>>(sc, pq1, pq2, ps, scale);

        // o = attn @ V (K truncated at diagonal)
        launch_imma<0, false, true>(dim3(KDIM / 128, SEQ / 128, BATCH),
            pq1, pq2, ps, vq1, vq2, vs, o, nullptr,
            SEQ, SEQ, SEQ, KDIM,
            (long)SEQ * SEQ, (long)KDIM * SEQ, (long)SEQ * KDIM, SEQ, KDIM);

        rowquant<<<MTOK, 256, KDIM * 4>>>(o, KDIM, KDIM, oq1, oq2, os);

        // x += o @ Wo^T
        launch_imma<1>(dim3(HDIM / 128, MTOK / 128, 1),
            oq1, oq2, os, wo1l, wo2l, wosl, x, nullptr, KDIM, KDIM, KDIM, HDIM);
        rowquant<<<MTOK, 256, HDIM * 4>>>(x, HDIM, HDIM, xq1, xq2, xs);

        // h = relu(x @ Wu^T + bu)
        launch_imma<2>(dim3(IDIM / 128, MTOK / 128, 1),
            xq1, xq2, xs, wu1l, wu2l, wusl, h, bu, HDIM, HDIM, HDIM, IDIM);
        rowquant<<<MTOK, 256, IDIM * 4>>>(h, IDIM, IDIM, hq1, hq2, hs);

        // x += h @ Wd^T + bd
        launch_imma<3>(dim3(HDIM / 128, MTOK / 128, 1),
            hq1, hq2, hs, wd1l, wd2l, wdsl, x, bd, IDIM, IDIM, IDIM, HDIM);
        rowquant<<<MTOK, 256, HDIM * 4>>>(x, HDIM, HDIM, xq1, xq2, xs);
    }

    // logits = x @ Wun^T + b
    launch_imma<4>(dim3(VOCAB / 128, MTOK / 128, 1),
        xq1, xq2, xs, wun1, wun2, sun, logits, unemb_b, HDIM, HDIM, HDIM, VOCAB);
}

// round 9
// speedup vs baseline: 3.0888x; 3.0888x over previous
#include <cuda_runtime.h>
#include <cuda_fp16.h>
#include <math.h>
#include <stdint.h>

#define LAYERS 8
#define HDIM   1024
#define KDIM   1024
#define IDIM   4096
#define VOCAB  32000
#define BATCH  2
#define SEQ    2048
#define MTOK   (BATCH * SEQ)

typedef __half h16;

// ---------------- scratch (device globals) ----------------
__device__ float g_x[(long)MTOK * HDIM];
__device__ float g_qkv[(long)MTOK * 3 * KDIM];
__device__ float g_scores[(long)BATCH * SEQ * SEQ];
__device__ h16 g_xh[(long)MTOK * HDIM],       g_xl[(long)MTOK * HDIM];
__device__ h16 g_qkvh[(long)MTOK * 3 * KDIM], g_qkvl[(long)MTOK * 3 * KDIM];
__device__ h16 g_sh[(long)BATCH * SEQ * SEQ], g_sl[(long)BATCH * SEQ * SEQ];
__device__ h16 g_vTh[(long)BATCH * KDIM * SEQ], g_vTl[(long)BATCH * KDIM * SEQ];
__device__ h16 g_oh[(long)MTOK * KDIM],       g_ol[(long)MTOK * KDIM];
__device__ h16 g_hh[(long)MTOK * IDIM],       g_hl[(long)MTOK * IDIM];
__device__ h16 g_qkvTh[(long)LAYERS * 3 * KDIM * HDIM], g_qkvTl[(long)LAYERS * 3 * KDIM * HDIM];
__device__ h16 g_oTh[(long)LAYERS * HDIM * KDIM],       g_oTl[(long)LAYERS * HDIM * KDIM];
__device__ h16 g_upTh[(long)LAYERS * IDIM * HDIM],      g_upTl[(long)LAYERS * IDIM * HDIM];
__device__ h16 g_dnTh[(long)LAYERS * HDIM * IDIM],      g_dnTl[(long)LAYERS * HDIM * IDIM];
__device__ h16 g_unTh[(long)VOCAB * HDIM],              g_unTl[(long)VOCAB * HDIM];

// ---------------- helpers ----------------
__device__ __forceinline__ uint32_t smem_u32(const void* p) {
    uint32_t a;
    asm("{ .reg .u64 t; cvta.to.shared.u64 t, %1; cvt.u32.u64 %0, t; }" : "=r"(a) : "l"(p));
    return a;
}
__device__ __forceinline__ void split1(float v, h16& h, h16& l) {
    h = __float2half_rn(v);
    l = __float2half_rn(v - __half2float(h));
}

#define CP_ASYNC16(dst, src) \
    asm volatile("cp.async.cg.shared.global [%0], [%1], 16;" :: "r"(dst), "l"(src) : "memory")
#define CP_COMMIT() asm volatile("cp.async.commit_group;" ::: "memory")
#define CP_WAIT1()  asm volatile("cp.async.wait_group 1;" ::: "memory")

#define LDSM_X4(r, a)                                                        \
    asm volatile("ldmatrix.sync.aligned.m8n8.x4.shared.b16 {%0,%1,%2,%3}, [%4];" \
        : "=r"((r)[0]), "=r"((r)[1]), "=r"((r)[2]), "=r"((r)[3]) : "r"(a))

__device__ __forceinline__ void mma_f16(float* c, const uint32_t* a,
                                        uint32_t b0, uint32_t b1) {
    asm volatile(
        "mma.sync.aligned.m16n8k16.row.col.f32.f16.f16.f32 "
        "{%0,%1,%2,%3}, {%4,%5,%6,%7}, {%8,%9}, {%0,%1,%2,%3};"
        : "+f"(c[0]), "+f"(c[1]), "+f"(c[2]), "+f"(c[3])
        : "r"(a[0]), "r"(a[1]), "r"(a[2]), "r"(a[3]), "r"(b0), "r"(b1));
}

// ---------------- embed (+split) ----------------
__global__ void embed_split(const int* __restrict__ tokens, const float* __restrict__ emb,
                            float* __restrict__ x, h16* __restrict__ xh, h16* __restrict__ xl) {
    int i = blockIdx.x;
    int tok = tokens[i];
    const float4* src = (const float4*)(emb + (long)tok * HDIM);
    float4* dst = (float4*)(x + (long)i * HDIM);
    for (int c = threadIdx.x; c < HDIM / 4; c += blockDim.x) {
        float4 v = src[c];
        dst[c] = v;
        h16 h0, l0, h1, l1, h2, l2, h3, l3;
        split1(v.x, h0, l0); split1(v.y, h1, l1);
        split1(v.z, h2, l2); split1(v.w, h3, l3);
        long base = (long)i * HDIM + c * 4;
        __half2 a = __halves2half2(h0, h1), b = __halves2half2(h2, h3);
        *(__half2*)(xh + base) = a; *(__half2*)(xh + base + 2) = b;
        a = __halves2half2(l0, l1); b = __halves2half2(l2, l3);
        *(__half2*)(xl + base) = a; *(__half2*)(xl + base + 2) = b;
    }
}

// ---------------- transpose + split (fp16 hi/lo) ----------------
__global__ void transpose_split(const float* __restrict__ src,
                                h16* __restrict__ dh, h16* __restrict__ dl,
                                int R, int lds, long sbatch, long dbatch) {
    __shared__ float t[32][33];
    src += (long)blockIdx.z * sbatch;
    dh  += (long)blockIdx.z * dbatch;
    dl  += (long)blockIdx.z * dbatch;
    int c0 = blockIdx.x << 5, r0 = blockIdx.y << 5;
    int x = threadIdx.x, y = threadIdx.y;
    #pragma unroll
    for (int i = y; i < 32; i += 8)
        t[i][x] = src[(long)(r0 + i) * lds + c0 + x];
    __syncthreads();
    #pragma unroll
    for (int j = y; j < 32; j += 8) {
        float v = t[x][j];
        h16 h, l; split1(v, h, l);
        long idx = (long)(c0 + j) * R + r0 + x;
        dh[idx] = h; dl[idx] = l;
    }
}

// ---------------- causal softmax -> split fp16 ----------------
__global__ void softmax_split(float* __restrict__ sc, h16* __restrict__ sh,
                              h16* __restrict__ sl, float scale) {
    int row = blockIdx.x;
    int s = row & (SEQ - 1);
    float* p = sc + (long)row * SEQ;
    h16* ph = sh + (long)row * SEQ;
    h16* pl = sl + (long)row * SEQ;
    int tid = threadIdx.x;
    __shared__ float red[256];

    float m = -INFINITY;
    for (int t = tid; t <= s; t += blockDim.x) m = fmaxf(m, p[t] * scale);
    red[tid] = m; __syncthreads();
    for (int o = 128; o > 0; o >>= 1) {
        if (tid < o) red[tid] = fmaxf(red[tid], red[tid + o]);
        __syncthreads();
    }
    m = red[0]; __syncthreads();

    float sum = 0.f;
    for (int t = tid; t <= s; t += blockDim.x) {
        float e = __expf(p[t] * scale - m);
        p[t] = e;
        sum += e;
    }
    red[tid] = sum; __syncthreads();
    for (int o = 128; o > 0; o >>= 1) {
        if (tid < o) red[tid] += red[tid + o];
        __syncthreads();
    }
    float inv = 1.f / red[0];
    const h16 z = __float2half(0.f);
    for (int t = tid; t <= s; t += blockDim.x) {
        h16 h, l; split1(p[t] * inv, h, l);
        ph[t] = h; pl[t] = l;
    }
    for (int t = s + 1 + tid; t < SEQ; t += blockDim.x) { ph[t] = z; pl[t] = z; }
}

// ---------------- HMMA GEMM: C[M,N] = A[M,K] @ B[N,K]^T --------------------
// CTA tile 128x256x32, 256 threads, 8 warps (2 M x 4 N), 64x64 warp tiles.
// fp16 hi/lo. PASSES=3: Ah*Bh + Ah*Bl + Al*Bh.  PASSES=2: Ah*Bh + Al*Bh.
// EPI: 0 none, 1 +=Cf, 2 relu(+bias), 3 +bias+Cf, 4 +bias
// CSKIP: skip blocks with n0 > m0+127.  CK: truncate K loop at m0+128.
#define DEPTH     3
#define MAT_A     10240u                  // 128 rows * 80B
#define MAT_B     20480u                  // 256 rows * 80B
#define STG_BYTES 61440u
#define SMEM_TOT  (DEPTH * STG_BYTES)

template<int EPI, bool F32OUT, bool SPLITOUT, bool CSKIP, bool CK, int PASSES>
__global__ __launch_bounds__(256, 1)
void mma_gemm(const h16* __restrict__ Ah, const h16* __restrict__ Al,
              const h16* __restrict__ Bh, const h16* __restrict__ Bl,
              float* __restrict__ Cf, h16* __restrict__ Ch, h16* __restrict__ Cl,
              const float* __restrict__ bias,
              int K, int lda, int ldb, int ldc,
              long bsA, long bsB, long bsC) {
    const int m0 = blockIdx.y << 7;
    const int n0 = blockIdx.x << 8;
    if (CSKIP && n0 > m0 + 127) return;

    const long zA = (long)blockIdx.z * bsA;
    const long zB = (long)blockIdx.z * bsB;
    const long zC = (long)blockIdx.z * bsC;

    extern __shared__ char smem[];
    const uint32_t sbase = smem_u32(smem);
    const int tid = threadIdx.x;
    const int lane = tid & 31, wid = tid >> 5;
    const int wm = wid & 1, wn = wid >> 1;
    int NK = K >> 5;
    if (CK) { int nke = (m0 + 128) >> 5; NK = (nke < NK) ? nke : NK; }
    constexpr int NROWI = (PASSES == 3) ? 12 : 8;

    const h16* gm[4] = { Ah + zA + (long)m0 * lda, Al + zA + (long)m0 * lda,
                         Bh + zB + (long)n0 * ldb, Bl + zB + (long)n0 * ldb };
    const int  ldm[4]  = { lda, lda, ldb, ldb };
    const uint32_t moff[4] = { 0u, MAT_A, 2u * MAT_A, 2u * MAT_A + MAT_B };
    const int rgrp = tid >> 2;
    const int atom = tid & 3;

    float acc[4][8][4];
    #pragma unroll
    for (int a = 0; a < 4; a++)
        #pragma unroll
        for (int b = 0; b < 8; b++)
            #pragma unroll
            for (int c = 0; c < 4; c++) acc[a][b][c] = 0.f;

    #define LOAD_STAGE(kt, slot) do {                                          \
        uint32_t st_ = sbase + (slot) * STG_BYTES;                             \
        _Pragma("unroll")                                                      \
        for (int i = 0; i < NROWI; i++) {                                      \
            const int mat = (i < 2) ? 0 : (i < 4) ? 1 : (i < 8) ? 2 : 3;       \
            const int lr  = (i - ((mat == 0) ? 0 : (mat == 1) ? 2 : (mat == 2) ? 4 : 8)) * 64 + rgrp; \
            const h16* g = gm[mat] + (long)lr * ldm[mat] + ((kt) << 5) + (atom << 3); \
            CP_ASYNC16(st_ + moff[mat] + (uint32_t)lr * 80u + (atom << 4), g); \
        }                                                                      \
        CP_COMMIT();                                                           \
    } while (0)

    LOAD_STAGE(0, 0);
    LOAD_STAGE(1, 1);

    for (int kt = 0; kt < NK; kt++) {
        CP_WAIT1();
        __syncthreads();
        if (kt + 2 < NK) { LOAD_STAGE(kt + 2, (kt + 2) % DEPTH); }
        else             { CP_COMMIT(); }

        uint32_t st = sbase + (kt % DEPTH) * STG_BYTES;
        #pragma unroll
        for (int s = 0; s < 2; s++) {
            uint32_t a_h[4][4], a_l[4][4];
            #pragma unroll
            for (int mt = 0; mt < 4; mt++) {
                uint32_t ad = st + (uint32_t)(wm * 64 + mt * 16 + (lane & 15)) * 80u
                              + s * 32 + ((lane >> 4) << 4);
                LDSM_X4(a_h[mt], ad);
                LDSM_X4(a_l[mt], ad + MAT_A);
            }
            #pragma unroll
            for (int p = 0; p < 4; p++) {
                uint32_t b_h[4], b_l[4];
                uint32_t bd = st + 2u * MAT_A
                              + (uint32_t)(wn * 64 + p * 16 + ((lane >> 4) << 3) + (lane & 7)) * 80u
                              + s * 32 + (((lane >> 3) & 1) << 4);
                LDSM_X4(b_h, bd);
                if (PASSES == 3) LDSM_X4(b_l, bd + MAT_B);
                #pragma unroll
                for (int q = 0; q < 2; q++) {
                    const int nt = p * 2 + q;
                    uint32_t bh0 = b_h[q * 2], bh1 = b_h[q * 2 + 1];
                    #pragma unroll
                    for (int mt = 0; mt < 4; mt++) {
                        mma_f16(acc[mt][nt], a_h[mt], bh0, bh1);
                        if (PASSES == 3)
                            mma_f16(acc[mt][nt], a_h[mt], b_l[q * 2], b_l[q * 2 + 1]);
                        mma_f16(acc[mt][nt], a_l[mt], bh0, bh1);
                    }
                }
            }
        }
    }

    // ---- epilogue ----
    #pragma unroll
    for (int mt = 0; mt < 4; mt++) {
        #pragma unroll
        for (int nt = 0; nt < 8; nt++) {
            int mbase = m0 + wm * 64 + mt * 16 + (lane >> 2);
            int n = n0 + wn * 64 + nt * 8 + (lane & 3) * 2;
            #pragma unroll
            for (int hf = 0; hf < 2; hf++) {
                int mm = mbase + hf * 8;
                float vx = acc[mt][nt][hf * 2 + 0];
                float vy = acc[mt][nt][hf * 2 + 1];
                long idx = zC + (long)mm * ldc + n;
                if (EPI >= 2) { vx += bias[n]; vy += bias[n + 1]; }
                if (EPI == 2) { vx = fmaxf(vx, 0.f); vy = fmaxf(vy, 0.f); }
                if (EPI == 1 || EPI == 3) {
                    float2 old = *(const float2*)(Cf + idx);
                    vx += old.x; vy += old.y;
                }
                if (F32OUT) {
                    float2 o; o.x = vx; o.y = vy;
                    *(float2*)(Cf + idx) = o;
                }
                if (SPLITOUT) {
                    h16 hx, lx, hy, ly;
                    split1(vx, hx, lx); split1(vy, hy, ly);
                    *(__half2*)(Ch + idx) = __halves2half2(hx, hy);
                    *(__half2*)(Cl + idx) = __halves2half2(lx, ly);
                }
            }
        }
    }
}

// ---------------- host ----------------
template<int EPI, bool F32O, bool SPL, bool CSKIP = false, bool CK = false, int PASSES = 3>
static void launch_mma(dim3 grid, const h16* Ah, const h16* Al,
                       const h16* Bh, const h16* Bl,
                       float* Cf, h16* Ch, h16* Cl, const float* bias,
                       int K, int lda, int ldb, int ldc,
                       long bsA = 0, long bsB = 0, long bsC = 0) {
    cudaFuncSetAttribute(mma_gemm<EPI, F32O, SPL, CSKIP, CK, PASSES>,
                         cudaFuncAttributeMaxDynamicSharedMemorySize, SMEM_TOT);
    mma_gemm<EPI, F32O, SPL, CSKIP, CK, PASSES><<<grid, 256, SMEM_TOT>>>(
        Ah, Al, Bh, Bl, Cf, Ch, Cl, bias, K, lda, ldb, ldc, bsA, bsB, bsC);
}

#define SYM(p, g) cudaGetSymbolAddress((void**)&p, g)

extern "C" void kernel_launch(void* const* d_in, const int* in_sizes, int n_in,
                              void* d_out, int out_size) {
    const int*   tokens    = (const int*)  d_in[0];
    const float* embedding = (const float*)d_in[1];
    const float* qkv_w     = (const float*)d_in[2];
    const float* o_w       = (const float*)d_in[3];
    const float* up_w      = (const float*)d_in[4];
    const float* up_b      = (const float*)d_in[5];
    const float* down_w    = (const float*)d_in[6];
    const float* down_b    = (const float*)d_in[7];
    const float* unemb_w   = (const float*)d_in[8];
    const float* unemb_b   = (const float*)d_in[9];
    float* logits = (float*)d_out;

    float *x, *qkv, *sc;
    h16 *xh, *xl, *qh, *ql, *sh, *sl, *vTh, *vTl, *oh, *ol, *hh, *hl;
    h16 *qkvTh, *qkvTl, *oTh, *oTl, *upTh, *upTl, *dnTh, *dnTl, *unTh, *unTl;
    SYM(x, g_x); SYM(qkv, g_qkv); SYM(sc, g_scores);
    SYM(xh, g_xh); SYM(xl, g_xl);
    SYM(qh, g_qkvh); SYM(ql, g_qkvl);
    SYM(sh, g_sh); SYM(sl, g_sl);
    SYM(vTh, g_vTh); SYM(vTl, g_vTl);
    SYM(oh, g_oh); SYM(ol, g_ol);
    SYM(hh, g_hh); SYM(hl, g_hl);
    SYM(qkvTh, g_qkvTh); SYM(qkvTl, g_qkvTl);
    SYM(oTh, g_oTh); SYM(oTl, g_oTl);
    SYM(upTh, g_upTh); SYM(upTl, g_upTl);
    SYM(dnTh, g_dnTh); SYM(dnTl, g_dnTl);
    SYM(unTh, g_unTh); SYM(unTl, g_unTl);

    const float scale = 1.0f / sqrtf((float)KDIM);
    dim3 tb(32, 8);

    transpose_split<<<dim3(3 * KDIM / 32, HDIM / 32, LAYERS), tb>>>(
        qkv_w, qkvTh, qkvTl, HDIM, 3 * KDIM, (long)HDIM * 3 * KDIM, (long)HDIM * 3 * KDIM);
    transpose_split<<<dim3(HDIM / 32, KDIM / 32, LAYERS), tb>>>(
        o_w, oTh, oTl, KDIM, HDIM, (long)KDIM * HDIM, (long)KDIM * HDIM);
    transpose_split<<<dim3(IDIM / 32, HDIM / 32, LAYERS), tb>>>(
        up_w, upTh, upTl, HDIM, IDIM, (long)HDIM * IDIM, (long)HDIM * IDIM);
    transpose_split<<<dim3(HDIM / 32, IDIM / 32, LAYERS), tb>>>(
        down_w, dnTh, dnTl, IDIM, HDIM, (long)IDIM * HDIM, (long)IDIM * HDIM);
    transpose_split<<<dim3(VOCAB / 32, HDIM / 32, 1), tb>>>(
        unemb_w, unTh, unTl, HDIM, VOCAB, 0, 0);

    embed_split<<<MTOK, 256>>>(tokens, embedding, x, xh, xl);

    for (int l = 0; l < LAYERS; l++) {
        h16* wqh = qkvTh + (long)l * 3 * KDIM * HDIM;
        h16* wql = qkvTl + (long)l * 3 * KDIM * HDIM;
        h16* woh = oTh   + (long)l * HDIM * KDIM;
        h16* wol = oTl   + (long)l * HDIM * KDIM;
        h16* wuh = upTh  + (long)l * IDIM * HDIM;
        h16* wul = upTl  + (long)l * IDIM * HDIM;
        h16* wdh = dnTh  + (long)l * HDIM * IDIM;
        h16* wdl = dnTl  + (long)l * HDIM * IDIM;
        const float* bu = up_b   + (long)l * IDIM;
        const float* bd = down_b + (long)l * HDIM;

        // qkv = x @ Wqkv  (3-pass) -> fp32 (for V transpose) + split
        launch_mma<0, true, true>(dim3(3 * KDIM / 256, MTOK / 128, 1),
            xh, xl, wqh, wql, qkv, qh, ql, nullptr, HDIM, HDIM, HDIM, 3 * KDIM);

        transpose_split<<<dim3(KDIM / 32, SEQ / 32, BATCH), tb>>>(
            qkv + 2 * KDIM, vTh, vTl, SEQ, 3 * KDIM,
            (long)SEQ * 3 * KDIM, (long)KDIM * SEQ);

        // scores = Q @ K^T  (3-pass, causal block skip)
        launch_mma<0, true, false, true, false>(dim3(SEQ / 256, SEQ / 128, BATCH),
            qh, ql, qh + KDIM, ql + KDIM, sc, nullptr, nullptr, nullptr,
            KDIM, 3 * KDIM, 3 * KDIM, SEQ,
            (long)SEQ * 3 * KDIM, (long)SEQ * 3 * KDIM, (long)SEQ * SEQ);

        softmax_split<<<BATCH * SEQ, 256>>>(sc, sh, sl, scale);

        // o = attn @ V  (3-pass, K truncated at diagonal)
        launch_mma<0, false, true, false, true>(dim3(KDIM / 256, SEQ / 128, BATCH),
            sh, sl, vTh, vTl, nullptr, oh, ol, nullptr,
            SEQ, SEQ, SEQ, KDIM,
            (long)SEQ * SEQ, (long)KDIM * SEQ, (long)SEQ * KDIM);

        // x += o @ Wo  (2-pass)
        launch_mma<1, true, true, false, false, 2>(dim3(HDIM / 256, MTOK / 128, 1),
            oh, ol, woh, wol, x, xh, xl, nullptr, KDIM, KDIM, KDIM, HDIM);

        // h = relu(x @ Wu + bu)  (2-pass)
        launch_mma<2, false, true, false, false, 2>(dim3(IDIM / 256, MTOK / 128, 1),
            xh, xl, wuh, wul, nullptr, hh, hl, bu, HDIM, HDIM, HDIM, IDIM);

        // x += h @ Wd + bd  (2-pass)
        launch_mma<3, true, true, false, false, 2>(dim3(HDIM / 256, MTOK / 128, 1),
            hh, hl, wdh, wdl, x, xh, xl, bd, IDIM, IDIM, IDIM, HDIM);
    }

    // logits = x @ Wun + b  (2-pass, consumes xh/xl directly)
    launch_mma<4, true, false, false, false, 2>(dim3(VOCAB / 256, MTOK / 128, 1),
        xh, xl, unTh, unTl, logits, nullptr, nullptr, unemb_b,
        HDIM, HDIM, HDIM, VOCAB);
}

// round 10
// speedup vs baseline: 3.5082x; 1.1358x over previous
#include <cuda_runtime.h>
#include <cuda_fp16.h>
#include <math.h>
#include <stdint.h>

#define LAYERS 8
#define HDIM   1024
#define KDIM   1024
#define IDIM   4096
#define VOCAB  32000
#define BATCH  2
#define SEQ    2048
#define MTOK   (BATCH * SEQ)

typedef __half h16;

// ---------------- scratch (device globals) ----------------
__device__ float g_x[(long)MTOK * HDIM];
__device__ float g_qkv[(long)MTOK * 3 * KDIM];
__device__ float g_scores[(long)BATCH * SEQ * SEQ];
__device__ h16 g_xh[(long)MTOK * HDIM],       g_xl[(long)MTOK * HDIM];
__device__ h16 g_qkvh[(long)MTOK * 3 * KDIM], g_qkvl[(long)MTOK * 3 * KDIM];
__device__ h16 g_sh[(long)BATCH * SEQ * SEQ], g_sl[(long)BATCH * SEQ * SEQ];
__device__ h16 g_vTh[(long)BATCH * KDIM * SEQ];
__device__ h16 g_oh[(long)MTOK * KDIM],       g_ol[(long)MTOK * KDIM];
__device__ h16 g_hh[(long)MTOK * IDIM],       g_hl[(long)MTOK * IDIM];
// single-fp16 transposed weights [N,K]
__device__ h16 g_qkvT[(long)LAYERS * 3 * KDIM * HDIM];
__device__ h16 g_oT[(long)LAYERS * HDIM * KDIM];
__device__ h16 g_upT[(long)LAYERS * IDIM * HDIM];
__device__ h16 g_dnT[(long)LAYERS * HDIM * IDIM];
__device__ h16 g_unT[(long)VOCAB * HDIM];

// ---------------- helpers ----------------
__device__ __forceinline__ uint32_t smem_u32(const void* p) {
    uint32_t a;
    asm("{ .reg .u64 t; cvta.to.shared.u64 t, %1; cvt.u32.u64 %0, t; }" : "=r"(a) : "l"(p));
    return a;
}
__device__ __forceinline__ void split1(float v, h16& h, h16& l) {
    h = __float2half_rn(v);
    l = __float2half_rn(v - __half2float(h));
}

#define CP_ASYNC16(dst, src) \
    asm volatile("cp.async.cg.shared.global [%0], [%1], 16;" :: "r"(dst), "l"(src) : "memory")
#define CP_COMMIT() asm volatile("cp.async.commit_group;" ::: "memory")
#define CP_WAIT1()  asm volatile("cp.async.wait_group 1;" ::: "memory")

#define LDSM_X4(r, a)                                                        \
    asm volatile("ldmatrix.sync.aligned.m8n8.x4.shared.b16 {%0,%1,%2,%3}, [%4];" \
        : "=r"((r)[0]), "=r"((r)[1]), "=r"((r)[2]), "=r"((r)[3]) : "r"(a))

__device__ __forceinline__ void mma_f16(float* c, const uint32_t* a,
                                        uint32_t b0, uint32_t b1) {
    asm volatile(
        "mma.sync.aligned.m16n8k16.row.col.f32.f16.f16.f32 "
        "{%0,%1,%2,%3}, {%4,%5,%6,%7}, {%8,%9}, {%0,%1,%2,%3};"
        : "+f"(c[0]), "+f"(c[1]), "+f"(c[2]), "+f"(c[3])
        : "r"(a[0]), "r"(a[1]), "r"(a[2]), "r"(a[3]), "r"(b0), "r"(b1));
}

// ---------------- embed (+split) ----------------
__global__ void embed_split(const int* __restrict__ tokens, const float* __restrict__ emb,
                            float* __restrict__ x, h16* __restrict__ xh, h16* __restrict__ xl) {
    int i = blockIdx.x;
    int tok = tokens[i];
    const float4* src = (const float4*)(emb + (long)tok * HDIM);
    float4* dst = (float4*)(x + (long)i * HDIM);
    for (int c = threadIdx.x; c < HDIM / 4; c += blockDim.x) {
        float4 v = src[c];
        dst[c] = v;
        h16 h0, l0, h1, l1, h2, l2, h3, l3;
        split1(v.x, h0, l0); split1(v.y, h1, l1);
        split1(v.z, h2, l2); split1(v.w, h3, l3);
        long base = (long)i * HDIM + c * 4;
        *(__half2*)(xh + base)     = __halves2half2(h0, h1);
        *(__half2*)(xh + base + 2) = __halves2half2(h2, h3);
        *(__half2*)(xl + base)     = __halves2half2(l0, l1);
        *(__half2*)(xl + base + 2) = __halves2half2(l2, l3);
    }
}

// ---------------- transpose -> single fp16 (batched) ----------------
__global__ void transpose_f16(const float* __restrict__ src, h16* __restrict__ dst,
                              int R, int lds, long sbatch, long dbatch) {
    __shared__ float t[32][33];
    src += (long)blockIdx.z * sbatch;
    dst += (long)blockIdx.z * dbatch;
    int c0 = blockIdx.x << 5, r0 = blockIdx.y << 5;
    int x = threadIdx.x, y = threadIdx.y;
    #pragma unroll
    for (int i = y; i < 32; i += 8)
        t[i][x] = src[(long)(r0 + i) * lds + c0 + x];
    __syncthreads();
    #pragma unroll
    for (int j = y; j < 32; j += 8)
        dst[(long)(c0 + j) * R + r0 + x] = __float2half_rn(t[x][j]);
}

// ---------------- causal softmax -> split fp16 ----------------
__global__ void softmax_split(float* __restrict__ sc, h16* __restrict__ sh,
                              h16* __restrict__ sl, float scale) {
    int row = blockIdx.x;
    int s = row & (SEQ - 1);
    float* p = sc + (long)row * SEQ;
    h16* ph = sh + (long)row * SEQ;
    h16* pl = sl + (long)row * SEQ;
    int tid = threadIdx.x;
    __shared__ float red[256];

    float m = -INFINITY;
    for (int t = tid; t <= s; t += blockDim.x) m = fmaxf(m, p[t] * scale);
    red[tid] = m; __syncthreads();
    for (int o = 128; o > 0; o >>= 1) {
        if (tid < o) red[tid] = fmaxf(red[tid], red[tid + o]);
        __syncthreads();
    }
    m = red[0]; __syncthreads();

    float sum = 0.f;
    for (int t = tid; t <= s; t += blockDim.x) {
        float e = __expf(p[t] * scale - m);
        p[t] = e;
        sum += e;
    }
    red[tid] = sum; __syncthreads();
    for (int o = 128; o > 0; o >>= 1) {
        if (tid < o) red[tid] += red[tid + o];
        __syncthreads();
    }
    float inv = 1.f / red[0];
    const h16 z = __float2half(0.f);
    for (int t = tid; t <= s; t += blockDim.x) {
        h16 h, l; split1(p[t] * inv, h, l);
        ph[t] = h; pl[t] = l;
    }
    for (int t = s + 1 + tid; t < SEQ; t += blockDim.x) { ph[t] = z; pl[t] = z; }
}

// ---------------- 2-pass HMMA GEMM: C = (Ah+Al) @ Bh^T ---------------------
// CTA tile 128x256x32, 256 threads, 8 warps (2 M x 4 N), 64x64 warp tiles.
// A exact fp16 hi/lo (2 passes), B single fp16.
// EPI: 0 none, 1 +=Cf, 2 relu(+bias), 3 +bias+Cf, 4 +bias
// CSKIP: skip blocks with n0 > m0+127.  CK: truncate K loop at m0+128.
#define DEPTH     3
#define MAT_A     10240u                  // 128 rows * 80B
#define MAT_B     20480u                  // 256 rows * 80B
#define STG_BYTES 40960u                  // 2*MAT_A + MAT_B
#define SMEM_TOT  (DEPTH * STG_BYTES)     // 122880

template<int EPI, bool F32OUT, bool SPLITOUT, bool CSKIP, bool CK>
__global__ __launch_bounds__(256, 1)
void mma_gemm(const h16* __restrict__ Ah, const h16* __restrict__ Al,
              const h16* __restrict__ Bh,
              float* __restrict__ Cf, h16* __restrict__ Ch, h16* __restrict__ Cl,
              const float* __restrict__ bias,
              int K, int lda, int ldb, int ldc,
              long bsA, long bsB, long bsC) {
    const int m0 = blockIdx.y << 7;
    const int n0 = blockIdx.x << 8;
    if (CSKIP && n0 > m0 + 127) return;

    const long zA = (long)blockIdx.z * bsA;
    const long zB = (long)blockIdx.z * bsB;
    const long zC = (long)blockIdx.z * bsC;

    extern __shared__ char smem[];
    const uint32_t sbase = smem_u32(smem);
    const int tid = threadIdx.x;
    const int lane = tid & 31, wid = tid >> 5;
    const int wm = wid & 1, wn = wid >> 1;
    int NK = K >> 5;
    if (CK) { int nke = (m0 + 128) >> 5; NK = (nke < NK) ? nke : NK; }

    const h16* gm[3] = { Ah + zA + (long)m0 * lda, Al + zA + (long)m0 * lda,
                         Bh + zB + (long)n0 * ldb };
    const int  ldm[3]  = { lda, lda, ldb };
    const uint32_t moff[3] = { 0u, MAT_A, 2u * MAT_A };
    const int rgrp = tid >> 2;        // 0..63
    const int atom = tid & 3;

    float acc[4][8][4];
    #pragma unroll
    for (int a = 0; a < 4; a++)
        #pragma unroll
        for (int b = 0; b < 8; b++)
            #pragma unroll
            for (int c = 0; c < 4; c++) acc[a][b][c] = 0.f;

    // i=0,1 -> A_h rows 0..127 ; i=2,3 -> A_l ; i=4..7 -> B_h rows 0..255
    #define LOAD_STAGE(kt, slot) do {                                          \
        uint32_t st_ = sbase + (slot) * STG_BYTES;                             \
        _Pragma("unroll")                                                      \
        for (int i = 0; i < 8; i++) {                                          \
            const int mat = (i < 2) ? 0 : (i < 4) ? 1 : 2;                     \
            const int lr  = (i - ((mat == 0) ? 0 : (mat == 1) ? 2 : 4)) * 64 + rgrp; \
            const h16* g = gm[mat] + (long)lr * ldm[mat] + ((kt) << 5) + (atom << 3); \
            CP_ASYNC16(st_ + moff[mat] + (uint32_t)lr * 80u + (atom << 4), g); \
        }                                                                      \
        CP_COMMIT();                                                           \
    } while (0)

    LOAD_STAGE(0, 0);
    LOAD_STAGE(1, 1);

    for (int kt = 0; kt < NK; kt++) {
        CP_WAIT1();
        __syncthreads();
        if (kt + 2 < NK) { LOAD_STAGE(kt + 2, (kt + 2) % DEPTH); }
        else             { CP_COMMIT(); }

        uint32_t st = sbase + (kt % DEPTH) * STG_BYTES;
        #pragma unroll
        for (int s = 0; s < 2; s++) {
            uint32_t a_h[4][4], a_l[4][4];
            #pragma unroll
            for (int mt = 0; mt < 4; mt++) {
                uint32_t ad = st + (uint32_t)(wm * 64 + mt * 16 + (lane & 15)) * 80u
                              + s * 32 + ((lane >> 4) << 4);
                LDSM_X4(a_h[mt], ad);
                LDSM_X4(a_l[mt], ad + MAT_A);
            }
            #pragma unroll
            for (int p = 0; p < 4; p++) {
                uint32_t b_h[4];
                uint32_t bd = st + 2u * MAT_A
                              + (uint32_t)(wn * 64 + p * 16 + ((lane >> 4) << 3) + (lane & 7)) * 80u
                              + s * 32 + (((lane >> 3) & 1) << 4);
                LDSM_X4(b_h, bd);
                #pragma unroll
                for (int q = 0; q < 2; q++) {
                    const int nt = p * 2 + q;
                    uint32_t bh0 = b_h[q * 2], bh1 = b_h[q * 2 + 1];
                    #pragma unroll
                    for (int mt = 0; mt < 4; mt++) {
                        mma_f16(acc[mt][nt], a_h[mt], bh0, bh1);
                        mma_f16(acc[mt][nt], a_l[mt], bh0, bh1);
                    }
                }
            }
        }
    }

    // ---- epilogue ----
    #pragma unroll
    for (int mt = 0; mt < 4; mt++) {
        #pragma unroll
        for (int nt = 0; nt < 8; nt++) {
            int mbase = m0 + wm * 64 + mt * 16 + (lane >> 2);
            int n = n0 + wn * 64 + nt * 8 + (lane & 3) * 2;
            #pragma unroll
            for (int hf = 0; hf < 2; hf++) {
                int mm = mbase + hf * 8;
                float vx = acc[mt][nt][hf * 2 + 0];
                float vy = acc[mt][nt][hf * 2 + 1];
                long idx = zC + (long)mm * ldc + n;
                if (EPI >= 2) { vx += bias[n]; vy += bias[n + 1]; }
                if (EPI == 2) { vx = fmaxf(vx, 0.f); vy = fmaxf(vy, 0.f); }
                if (EPI == 1 || EPI == 3) {
                    float2 old = *(const float2*)(Cf + idx);
                    vx += old.x; vy += old.y;
                }
                if (F32OUT) {
                    float2 o; o.x = vx; o.y = vy;
                    *(float2*)(Cf + idx) = o;
                }
                if (SPLITOUT) {
                    h16 hx, lx, hy, ly;
                    split1(vx, hx, lx); split1(vy, hy, ly);
                    *(__half2*)(Ch + idx) = __halves2half2(hx, hy);
                    *(__half2*)(Cl + idx) = __halves2half2(lx, ly);
                }
            }
        }
    }
}

// ---------------- host ----------------
template<int EPI, bool F32O, bool SPL, bool CSKIP = false, bool CK = false>
static void launch_mma(dim3 grid, const h16* Ah, const h16* Al, const h16* Bh,
                       float* Cf, h16* Ch, h16* Cl, const float* bias,
                       int K, int lda, int ldb, int ldc,
                       long bsA = 0, long bsB = 0, long bsC = 0) {
    cudaFuncSetAttribute(mma_gemm<EPI, F32O, SPL, CSKIP, CK>,
                         cudaFuncAttributeMaxDynamicSharedMemorySize, SMEM_TOT);
    mma_gemm<EPI, F32O, SPL, CSKIP, CK><<<grid, 256, SMEM_TOT>>>(
        Ah, Al, Bh, Cf, Ch, Cl, bias, K, lda, ldb, ldc, bsA, bsB, bsC);
}

#define SYM(p, g) cudaGetSymbolAddress((void**)&p, g)

extern "C" void kernel_launch(void* const* d_in, const int* in_sizes, int n_in,
                              void* d_out, int out_size) {
    const int*   tokens    = (const int*)  d_in[0];
    const float* embedding = (const float*)d_in[1];
    const float* qkv_w     = (const float*)d_in[2];
    const float* o_w       = (const float*)d_in[3];
    const float* up_w      = (const float*)d_in[4];
    const float* up_b      = (const float*)d_in[5];
    const float* down_w    = (const float*)d_in[6];
    const float* down_b    = (const float*)d_in[7];
    const float* unemb_w   = (const float*)d_in[8];
    const float* unemb_b   = (const float*)d_in[9];
    float* logits = (float*)d_out;

    float *x, *qkv, *sc;
    h16 *xh, *xl, *qh, *ql, *sh, *sl, *vTh, *oh, *ol, *hh, *hl;
    h16 *qkvT, *oT, *upT, *dnT, *unT;
    SYM(x, g_x); SYM(qkv, g_qkv); SYM(sc, g_scores);
    SYM(xh, g_xh); SYM(xl, g_xl);
    SYM(qh, g_qkvh); SYM(ql, g_qkvl);
    SYM(sh, g_sh); SYM(sl, g_sl);
    SYM(vTh, g_vTh);
    SYM(oh, g_oh); SYM(ol, g_ol);
    SYM(hh, g_hh); SYM(hl, g_hl);
    SYM(qkvT, g_qkvT); SYM(oT, g_oT); SYM(upT, g_upT); SYM(dnT, g_dnT); SYM(unT, g_unT);

    const float scale = 1.0f / sqrtf((float)KDIM);
    dim3 tb(32, 8);

    // weight transposes -> [N,K] single fp16
    transpose_f16<<<dim3(3 * KDIM / 32, HDIM / 32, LAYERS), tb>>>(
        qkv_w, qkvT, HDIM, 3 * KDIM, (long)HDIM * 3 * KDIM, (long)HDIM * 3 * KDIM);
    transpose_f16<<<dim3(HDIM / 32, KDIM / 32, LAYERS), tb>>>(
        o_w, oT, KDIM, HDIM, (long)KDIM * HDIM, (long)KDIM * HDIM);
    transpose_f16<<<dim3(IDIM / 32, HDIM / 32, LAYERS), tb>>>(
        up_w, upT, HDIM, IDIM, (long)HDIM * IDIM, (long)HDIM * IDIM);
    transpose_f16<<<dim3(HDIM / 32, IDIM / 32, LAYERS), tb>>>(
        down_w, dnT, IDIM, HDIM, (long)IDIM * HDIM, (long)IDIM * HDIM);
    transpose_f16<<<dim3(VOCAB / 32, HDIM / 32, 1), tb>>>(
        unemb_w, unT, HDIM, VOCAB, 0, 0);

    embed_split<<<MTOK, 256>>>(tokens, embedding, x, xh, xl);

    for (int l = 0; l < LAYERS; l++) {
        h16* wq = qkvT + (long)l * 3 * KDIM * HDIM;
        h16* wo = oT   + (long)l * HDIM * KDIM;
        h16* wu = upT  + (long)l * IDIM * HDIM;
        h16* wd = dnT  + (long)l * HDIM * IDIM;
        const float* bu = up_b   + (long)l * IDIM;
        const float* bd = down_b + (long)l * HDIM;

        // qkv = x @ Wqkv -> fp32 (for V transpose) + split (Q A-side, K B-side)
        launch_mma<0, true, true>(dim3(3 * KDIM / 256, MTOK / 128, 1),
            xh, xl, wq, qkv, qh, ql, nullptr, HDIM, HDIM, HDIM, 3 * KDIM);

        // vT[b][k][t] = fp16(V[b][t][k])
        transpose_f16<<<dim3(KDIM / 32, SEQ / 32, BATCH), tb>>>(
            qkv + 2 * KDIM, vTh, SEQ, 3 * KDIM,
            (long)SEQ * 3 * KDIM, (long)KDIM * SEQ);

        // scores = Q @ K^T (A = Q split, B = K hi; causal block skip)
        launch_mma<0, true, false, true, false>(dim3(SEQ / 256, SEQ / 128, BATCH),
            qh, ql, qh + KDIM, sc, nullptr, nullptr, nullptr,
            KDIM, 3 * KDIM, 3 * KDIM, SEQ,
            (long)SEQ * 3 * KDIM, (long)SEQ * 3 * KDIM, (long)SEQ * SEQ);

        softmax_split<<<BATCH * SEQ, 256>>>(sc, sh, sl, scale);

        // o = attn @ V (A = probs split, B = vT hi; K truncated at diagonal)
        launch_mma<0, false, true, false, true>(dim3(KDIM / 256, SEQ / 128, BATCH),
            sh, sl, vTh, nullptr, oh, ol, nullptr,
            SEQ, SEQ, SEQ, KDIM,
            (long)SEQ * SEQ, (long)KDIM * SEQ, (long)SEQ * KDIM);

        // x += o @ Wo
        launch_mma<1, true, true>(dim3(HDIM / 256, MTOK / 128, 1),
            oh, ol, wo, x, xh, xl, nullptr, KDIM, KDIM, KDIM, HDIM);

        // h = relu(x @ Wu + bu)
        launch_mma<2, false, true>(dim3(IDIM / 256, MTOK / 128, 1),
            xh, xl, wu, nullptr, hh, hl, bu, HDIM, HDIM, HDIM, IDIM);

        // x += h @ Wd + bd
        launch_mma<3, true, true>(dim3(HDIM / 256, MTOK / 128, 1),
            hh, hl, wd, x, xh, xl, bd, IDIM, IDIM, IDIM, HDIM);
    }

    // logits = x @ Wun + b
    launch_mma<4, true, false>(dim3(VOCAB / 256, MTOK / 128, 1),
        xh, xl, unT, logits, nullptr, nullptr, unemb_b,
        HDIM, HDIM, HDIM, VOCAB);
}

// round 11
// speedup vs baseline: 3.7167x; 1.0594x over previous
#include <cuda_runtime.h>
#include <cuda_fp16.h>
#include <math.h>
#include <stdint.h>

#define LAYERS 8
#define HDIM   1024
#define KDIM   1024
#define IDIM   4096
#define VOCAB  32000
#define BATCH  2
#define SEQ    2048
#define MTOK   (BATCH * SEQ)

typedef __half h16;

// ---------------- scratch (device globals) ----------------
__device__ float g_x[(long)MTOK * HDIM];
__device__ float g_qkv[(long)MTOK * 3 * KDIM];
__device__ float g_scores[(long)BATCH * SEQ * SEQ];
__device__ h16 g_xh[(long)MTOK * HDIM],       g_xl[(long)MTOK * HDIM];
__device__ h16 g_qkvh[(long)MTOK * 3 * KDIM], g_qkvl[(long)MTOK * 3 * KDIM];
__device__ h16 g_sh[(long)BATCH * SEQ * SEQ];
__device__ h16 g_vTh[(long)BATCH * KDIM * SEQ];
__device__ h16 g_oh[(long)MTOK * KDIM],       g_ol[(long)MTOK * KDIM];
__device__ h16 g_hh[(long)MTOK * IDIM],       g_hl[(long)MTOK * IDIM];
// single-fp16 transposed weights [N,K]
__device__ h16 g_qkvT[(long)LAYERS * 3 * KDIM * HDIM];
__device__ h16 g_oT[(long)LAYERS * HDIM * KDIM];
__device__ h16 g_upT[(long)LAYERS * IDIM * HDIM];
__device__ h16 g_dnT[(long)LAYERS * HDIM * IDIM];
__device__ h16 g_unT[(long)VOCAB * HDIM];

// ---------------- helpers ----------------
__device__ __forceinline__ uint32_t smem_u32(const void* p) {
    uint32_t a;
    asm("{ .reg .u64 t; cvta.to.shared.u64 t, %1; cvt.u32.u64 %0, t; }" : "=r"(a) : "l"(p));
    return a;
}
__device__ __forceinline__ void split1(float v, h16& h, h16& l) {
    h = __float2half_rn(v);
    l = __float2half_rn(v - __half2float(h));
}

#define CP_ASYNC16(dst, src) \
    asm volatile("cp.async.cg.shared.global [%0], [%1], 16;" :: "r"(dst), "l"(src) : "memory")
#define CP_COMMIT() asm volatile("cp.async.commit_group;" ::: "memory")
#define CP_WAIT1()  asm volatile("cp.async.wait_group 1;" ::: "memory")

#define LDSM_X4(r, a)                                                        \
    asm volatile("ldmatrix.sync.aligned.m8n8.x4.shared.b16 {%0,%1,%2,%3}, [%4];" \
        : "=r"((r)[0]), "=r"((r)[1]), "=r"((r)[2]), "=r"((r)[3]) : "r"(a))

__device__ __forceinline__ void mma_f16(float* c, const uint32_t* a,
                                        uint32_t b0, uint32_t b1) {
    asm volatile(
        "mma.sync.aligned.m16n8k16.row.col.f32.f16.f16.f32 "
        "{%0,%1,%2,%3}, {%4,%5,%6,%7}, {%8,%9}, {%0,%1,%2,%3};"
        : "+f"(c[0]), "+f"(c[1]), "+f"(c[2]), "+f"(c[3])
        : "r"(a[0]), "r"(a[1]), "r"(a[2]), "r"(a[3]), "r"(b0), "r"(b1));
}

// ---------------- embed (+split) ----------------
__global__ void embed_split(const int* __restrict__ tokens, const float* __restrict__ emb,
                            float* __restrict__ x, h16* __restrict__ xh, h16* __restrict__ xl) {
    int i = blockIdx.x;
    int tok = tokens[i];
    const float4* src = (const float4*)(emb + (long)tok * HDIM);
    float4* dst = (float4*)(x + (long)i * HDIM);
    for (int c = threadIdx.x; c < HDIM / 4; c += blockDim.x) {
        float4 v = src[c];
        dst[c] = v;
        h16 h0, l0, h1, l1, h2, l2, h3, l3;
        split1(v.x, h0, l0); split1(v.y, h1, l1);
        split1(v.z, h2, l2); split1(v.w, h3, l3);
        long base = (long)i * HDIM + c * 4;
        *(__half2*)(xh + base)     = __halves2half2(h0, h1);
        *(__half2*)(xh + base + 2) = __halves2half2(h2, h3);
        *(__half2*)(xl + base)     = __halves2half2(l0, l1);
        *(__half2*)(xl + base + 2) = __halves2half2(l2, l3);
    }
}

// ---------------- transpose -> single fp16 (batched) ----------------
__global__ void transpose_f16(const float* __restrict__ src, h16* __restrict__ dst,
                              int R, int lds, long sbatch, long dbatch) {
    __shared__ float t[32][33];
    src += (long)blockIdx.z * sbatch;
    dst += (long)blockIdx.z * dbatch;
    int c0 = blockIdx.x << 5, r0 = blockIdx.y << 5;
    int x = threadIdx.x, y = threadIdx.y;
    #pragma unroll
    for (int i = y; i < 32; i += 8)
        t[i][x] = src[(long)(r0 + i) * lds + c0 + x];
    __syncthreads();
    #pragma unroll
    for (int j = y; j < 32; j += 8)
        dst[(long)(c0 + j) * R + r0 + x] = __float2half_rn(t[x][j]);
}

// ---------------- causal softmax -> fp16 (single) ----------------
__global__ void softmax_f16(float* __restrict__ sc, h16* __restrict__ sh, float scale) {
    int row = blockIdx.x;
    int s = row & (SEQ - 1);
    float* p = sc + (long)row * SEQ;
    h16* ph = sh + (long)row * SEQ;
    int tid = threadIdx.x;
    __shared__ float red[256];

    float m = -INFINITY;
    for (int t = tid; t <= s; t += blockDim.x) m = fmaxf(m, p[t] * scale);
    red[tid] = m; __syncthreads();
    for (int o = 128; o > 0; o >>= 1) {
        if (tid < o) red[tid] = fmaxf(red[tid], red[tid + o]);
        __syncthreads();
    }
    m = red[0]; __syncthreads();

    float sum = 0.f;
    for (int t = tid; t <= s; t += blockDim.x) {
        float e = __expf(p[t] * scale - m);
        p[t] = e;
        sum += e;
    }
    red[tid] = sum; __syncthreads();
    for (int o = 128; o > 0; o >>= 1) {
        if (tid < o) red[tid] += red[tid + o];
        __syncthreads();
    }
    float inv = 1.f / red[0];
    const h16 z = __float2half(0.f);
    for (int t = tid; t <= s; t += blockDim.x)
        ph[t] = __float2half_rn(p[t] * inv);
    for (int t = s + 1 + tid; t < SEQ; t += blockDim.x) ph[t] = z;
}

// ---------------- HMMA GEMM: C = (Ah [+Al]) @ Bh^T --------------------------
// CTA tile 128x256x32, 256 threads, 8 warps (2 M x 4 N), 64x64 warp tiles.
// PASSES=2: A exact fp16 hi/lo.  PASSES=1: A single fp16 (Al unused).
// EPI: 0 none, 1 +=Cf, 2 relu(+bias), 3 +bias+Cf, 4 +bias
// CSKIP: skip blocks with n0 > m0+127.  CK: truncate K loop at m0+128.
#define DEPTH     3
#define MAT_A     10240u                  // 128 rows * 80B
#define MAT_B     20480u                  // 256 rows * 80B
#define STG_BYTES 40960u                  // 2*MAT_A + MAT_B
#define SMEM_TOT  (DEPTH * STG_BYTES)     // 122880

template<int EPI, bool F32OUT, bool SPLITOUT, bool CSKIP, bool CK, int PASSES>
__global__ __launch_bounds__(256, 1)
void mma_gemm(const h16* __restrict__ Ah, const h16* __restrict__ Al,
              const h16* __restrict__ Bh,
              float* __restrict__ Cf, h16* __restrict__ Ch, h16* __restrict__ Cl,
              const float* __restrict__ bias,
              int K, int lda, int ldb, int ldc,
              long bsA, long bsB, long bsC) {
    const int m0 = blockIdx.y << 7;
    const int n0 = blockIdx.x << 8;
    if (CSKIP && n0 > m0 + 127) return;

    const long zA = (long)blockIdx.z * bsA;
    const long zB = (long)blockIdx.z * bsB;
    const long zC = (long)blockIdx.z * bsC;

    extern __shared__ char smem[];
    const uint32_t sbase = smem_u32(smem);
    const int tid = threadIdx.x;
    const int lane = tid & 31, wid = tid >> 5;
    const int wm = wid & 1, wn = wid >> 1;
    int NK = K >> 5;
    if (CK) { int nke = (m0 + 128) >> 5; NK = (nke < NK) ? nke : NK; }

    const h16* gm[3] = { Ah + zA + (long)m0 * lda, Al + zA + (long)m0 * lda,
                         Bh + zB + (long)n0 * ldb };
    const int  ldm[3]  = { lda, lda, ldb };
    const uint32_t moff[3] = { 0u, MAT_A, 2u * MAT_A };
    const int rgrp = tid >> 2;        // 0..63
    const int atom = tid & 3;
    constexpr int NROWI = (PASSES == 2) ? 8 : 6;

    float acc[4][8][4];
    #pragma unroll
    for (int a = 0; a < 4; a++)
        #pragma unroll
        for (int b = 0; b < 8; b++)
            #pragma unroll
            for (int c = 0; c < 4; c++) acc[a][b][c] = 0.f;

    // PASSES=2: i=0,1 -> A_h ; i=2,3 -> A_l ; i=4..7 -> B_h (256 rows)
    // PASSES=1: i=0,1 -> A_h ; i=2..5 -> B_h
    #define LOAD_STAGE(kt, slot) do {                                          \
        uint32_t st_ = sbase + (slot) * STG_BYTES;                             \
        _Pragma("unroll")                                                      \
        for (int i = 0; i < NROWI; i++) {                                      \
            int mat, lr;                                                       \
            if (PASSES == 2) {                                                 \
                mat = (i < 2) ? 0 : (i < 4) ? 1 : 2;                           \
                lr  = (i - ((mat == 0) ? 0 : (mat == 1) ? 2 : 4)) * 64 + rgrp; \
            } else {                                                           \
                mat = (i < 2) ? 0 : 2;                                         \
                lr  = (i - ((mat == 0) ? 0 : 2)) * 64 + rgrp;                  \
            }                                                                  \
            const h16* g = gm[mat] + (long)lr * ldm[mat] + ((kt) << 5) + (atom << 3); \
            CP_ASYNC16(st_ + moff[mat] + (uint32_t)lr * 80u + (atom << 4), g); \
        }                                                                      \
        CP_COMMIT();                                                           \
    } while (0)

    LOAD_STAGE(0, 0);
    LOAD_STAGE(1, 1);

    for (int kt = 0; kt < NK; kt++) {
        CP_WAIT1();
        __syncthreads();
        if (kt + 2 < NK) { LOAD_STAGE(kt + 2, (kt + 2) % DEPTH); }
        else             { CP_COMMIT(); }

        uint32_t st = sbase + (kt % DEPTH) * STG_BYTES;
        #pragma unroll
        for (int s = 0; s < 2; s++) {
            uint32_t a_h[4][4], a_l[4][4];
            #pragma unroll
            for (int mt = 0; mt < 4; mt++) {
                uint32_t ad = st + (uint32_t)(wm * 64 + mt * 16 + (lane & 15)) * 80u
                              + s * 32 + ((lane >> 4) << 4);
                LDSM_X4(a_h[mt], ad);
                if (PASSES == 2) LDSM_X4(a_l[mt], ad + MAT_A);
            }
            #pragma unroll
            for (int p = 0; p < 4; p++) {
                uint32_t b_h[4];
                uint32_t bd = st + 2u * MAT_A
                              + (uint32_t)(wn * 64 + p * 16 + ((lane >> 4) << 3) + (lane & 7)) * 80u
                              + s * 32 + (((lane >> 3) & 1) << 4);
                LDSM_X4(b_h, bd);
                #pragma unroll
                for (int q = 0; q < 2; q++) {
                    const int nt = p * 2 + q;
                    uint32_t bh0 = b_h[q * 2], bh1 = b_h[q * 2 + 1];
                    #pragma unroll
                    for (int mt = 0; mt < 4; mt++) {
                        mma_f16(acc[mt][nt], a_h[mt], bh0, bh1);
                        if (PASSES == 2) mma_f16(acc[mt][nt], a_l[mt], bh0, bh1);
                    }
                }
            }
        }
    }

    // ---- epilogue ----
    #pragma unroll
    for (int mt = 0; mt < 4; mt++) {
        #pragma unroll
        for (int nt = 0; nt < 8; nt++) {
            int mbase = m0 + wm * 64 + mt * 16 + (lane >> 2);
            int n = n0 + wn * 64 + nt * 8 + (lane & 3) * 2;
            #pragma unroll
            for (int hf = 0; hf < 2; hf++) {
                int mm = mbase + hf * 8;
                float vx = acc[mt][nt][hf * 2 + 0];
                float vy = acc[mt][nt][hf * 2 + 1];
                long idx = zC + (long)mm * ldc + n;
                if (EPI >= 2) { vx += bias[n]; vy += bias[n + 1]; }
                if (EPI == 2) { vx = fmaxf(vx, 0.f); vy = fmaxf(vy, 0.f); }
                if (EPI == 1 || EPI == 3) {
                    float2 old = *(const float2*)(Cf + idx);
                    vx += old.x; vy += old.y;
                }
                if (F32OUT) {
                    float2 o; o.x = vx; o.y = vy;
                    *(float2*)(Cf + idx) = o;
                }
                if (SPLITOUT) {
                    h16 hx, lx, hy, ly;
                    split1(vx, hx, lx); split1(vy, hy, ly);
                    *(__half2*)(Ch + idx) = __halves2half2(hx, hy);
                    *(__half2*)(Cl + idx) = __halves2half2(lx, ly);
                }
            }
        }
    }
}

// ---------------- host ----------------
template<int EPI, bool F32O, bool SPL, bool CSKIP = false, bool CK = false, int PASSES = 2>
static void launch_mma(dim3 grid, const h16* Ah, const h16* Al, const h16* Bh,
                       float* Cf, h16* Ch, h16* Cl, const float* bias,
                       int K, int lda, int ldb, int ldc,
                       long bsA = 0, long bsB = 0, long bsC = 0) {
    cudaFuncSetAttribute(mma_gemm<EPI, F32O, SPL, CSKIP, CK, PASSES>,
                         cudaFuncAttributeMaxDynamicSharedMemorySize, SMEM_TOT);
    mma_gemm<EPI, F32O, SPL, CSKIP, CK, PASSES><<<grid, 256, SMEM_TOT>>>(
        Ah, Al, Bh, Cf, Ch, Cl, bias, K, lda, ldb, ldc, bsA, bsB, bsC);
}

#define SYM(p, g) cudaGetSymbolAddress((void**)&p, g)

extern "C" void kernel_launch(void* const* d_in, const int* in_sizes, int n_in,
                              void* d_out, int out_size) {
    const int*   tokens    = (const int*)  d_in[0];
    const float* embedding = (const float*)d_in[1];
    const float* qkv_w     = (const float*)d_in[2];
    const float* o_w       = (const float*)d_in[3];
    const float* up_w      = (const float*)d_in[4];
    const float* up_b      = (const float*)d_in[5];
    const float* down_w    = (const float*)d_in[6];
    const float* down_b    = (const float*)d_in[7];
    const float* unemb_w   = (const float*)d_in[8];
    const float* unemb_b   = (const float*)d_in[9];
    float* logits = (float*)d_out;

    float *x, *qkv, *sc;
    h16 *xh, *xl, *qh, *ql, *sh, *vTh, *oh, *ol, *hh, *hl;
    h16 *qkvT, *oT, *upT, *dnT, *unT;
    SYM(x, g_x); SYM(qkv, g_qkv); SYM(sc, g_scores);
    SYM(xh, g_xh); SYM(xl, g_xl);
    SYM(qh, g_qkvh); SYM(ql, g_qkvl);
    SYM(sh, g_sh);
    SYM(vTh, g_vTh);
    SYM(oh, g_oh); SYM(ol, g_ol);
    SYM(hh, g_hh); SYM(hl, g_hl);
    SYM(qkvT, g_qkvT); SYM(oT, g_oT); SYM(upT, g_upT); SYM(dnT, g_dnT); SYM(unT, g_unT);

    const float scale = 1.0f / sqrtf((float)KDIM);
    dim3 tb(32, 8);

    // weight transposes -> [N,K] single fp16
    transpose_f16<<<dim3(3 * KDIM / 32, HDIM / 32, LAYERS), tb>>>(
        qkv_w, qkvT, HDIM, 3 * KDIM, (long)HDIM * 3 * KDIM, (long)HDIM * 3 * KDIM);
    transpose_f16<<<dim3(HDIM / 32, KDIM / 32, LAYERS), tb>>>(
        o_w, oT, KDIM, HDIM, (long)KDIM * HDIM, (long)KDIM * HDIM);
    transpose_f16<<<dim3(IDIM / 32, HDIM / 32, LAYERS), tb>>>(
        up_w, upT, HDIM, IDIM, (long)HDIM * IDIM, (long)HDIM * IDIM);
    transpose_f16<<<dim3(HDIM / 32, IDIM / 32, LAYERS), tb>>>(
        down_w, dnT, IDIM, HDIM, (long)IDIM * HDIM, (long)IDIM * HDIM);
    transpose_f16<<<dim3(VOCAB / 32, HDIM / 32, 1), tb>>>(
        unemb_w, unT, HDIM, VOCAB, 0, 0);

    embed_split<<<MTOK, 256>>>(tokens, embedding, x, xh, xl);

    for (int l = 0; l < LAYERS; l++) {
        h16* wq = qkvT + (long)l * 3 * KDIM * HDIM;
        h16* wo = oT   + (long)l * HDIM * KDIM;
        h16* wu = upT  + (long)l * IDIM * HDIM;
        h16* wd = dnT  + (long)l * HDIM * IDIM;
        const float* bu = up_b   + (long)l * IDIM;
        const float* bd = down_b + (long)l * HDIM;

        // qkv = x @ Wqkv (2-pass) -> fp32 (for V transpose) + split
        launch_mma<0, true, true>(dim3(3 * KDIM / 256, MTOK / 128, 1),
            xh, xl, wq, qkv, qh, ql, nullptr, HDIM, HDIM, HDIM, 3 * KDIM);

        // vT[b][k][t] = fp16(V[b][t][k])
        transpose_f16<<<dim3(KDIM / 32, SEQ / 32, BATCH), tb>>>(
            qkv + 2 * KDIM, vTh, SEQ, 3 * KDIM,
            (long)SEQ * 3 * KDIM, (long)KDIM * SEQ);

        // scores = Q @ K^T (1-pass: A = Q hi; causal block skip)
        launch_mma<0, true, false, true, false, 1>(dim3(SEQ / 256, SEQ / 128, BATCH),
            qh, qh, qh + KDIM, sc, nullptr, nullptr, nullptr,
            KDIM, 3 * KDIM, 3 * KDIM, SEQ,
            (long)SEQ * 3 * KDIM, (long)SEQ * 3 * KDIM, (long)SEQ * SEQ);

        softmax_f16<<<BATCH * SEQ, 256>>>(sc, sh, scale);

        // o = attn @ V (1-pass: A = probs fp16; K truncated at diagonal)
        launch_mma<0, false, true, false, true, 1>(dim3(KDIM / 256, SEQ / 128, BATCH),
            sh, sh, vTh, nullptr, oh, ol, nullptr,
            SEQ, SEQ, SEQ, KDIM,
            (long)SEQ * SEQ, (long)KDIM * SEQ, (long)SEQ * KDIM);

        // x += o @ Wo (2-pass)
        launch_mma<1, true, true>(dim3(HDIM / 256, MTOK / 128, 1),
            oh, ol, wo, x, xh, xl, nullptr, KDIM, KDIM, KDIM, HDIM);

        // h = relu(x @ Wu + bu) (2-pass)
        launch_mma<2, false, true>(dim3(IDIM / 256, MTOK / 128, 1),
            xh, xl, wu, nullptr, hh, hl, bu, HDIM, HDIM, HDIM, IDIM);

        // x += h @ Wd + bd (2-pass)
        launch_mma<3, true, true>(dim3(HDIM / 256, MTOK / 128, 1),
            hh, hl, wd, x, xh, xl, bd, IDIM, IDIM, IDIM, HDIM);
    }

    // logits = x @ Wun + b (2-pass)
    launch_mma<4, true, false>(dim3(VOCAB / 256, MTOK / 128, 1),
        xh, xl, unT, logits, nullptr, nullptr, unemb_b,
        HDIM, HDIM, HDIM, VOCAB);
}

// round 12
// speedup vs baseline: 4.2785x; 1.1512x over previous
#include <cuda_runtime.h>
#include <cuda_fp16.h>
#include <math.h>
#include <stdint.h>

#define LAYERS 8
#define HDIM   1024
#define KDIM   1024
#define IDIM   4096
#define VOCAB  32000
#define BATCH  2
#define SEQ    2048
#define MTOK   (BATCH * SEQ)

typedef __half h16;

// ---------------- scratch (device globals) ----------------
__device__ float g_x[(long)MTOK * HDIM];
__device__ float g_qkv[(long)MTOK * 3 * KDIM];
__device__ float g_scores[(long)BATCH * SEQ * SEQ];
__device__ h16 g_xh[(long)MTOK * HDIM],       g_xl[(long)MTOK * HDIM];
__device__ h16 g_qkvh[(long)MTOK * 3 * KDIM], g_qkvl[(long)MTOK * 3 * KDIM];
__device__ h16 g_sh[(long)BATCH * SEQ * SEQ];
__device__ h16 g_vTh[(long)BATCH * KDIM * SEQ];
__device__ h16 g_oh[(long)MTOK * KDIM],       g_ol[(long)MTOK * KDIM];
__device__ h16 g_hh[(long)MTOK * IDIM],       g_hl[(long)MTOK * IDIM];
// single-fp16 transposed weights [N,K]
__device__ h16 g_qkvT[(long)LAYERS * 3 * KDIM * HDIM];
__device__ h16 g_oT[(long)LAYERS * HDIM * KDIM];
__device__ h16 g_upT[(long)LAYERS * IDIM * HDIM];
__device__ h16 g_dnT[(long)LAYERS * HDIM * IDIM];
__device__ h16 g_unT[(long)VOCAB * HDIM];

// ---------------- helpers ----------------
__device__ __forceinline__ uint32_t smem_u32(const void* p) {
    uint32_t a;
    asm("{ .reg .u64 t; cvta.to.shared.u64 t, %1; cvt.u32.u64 %0, t; }" : "=r"(a) : "l"(p));
    return a;
}
__device__ __forceinline__ void split1(float v, h16& h, h16& l) {
    h = __float2half_rn(v);
    l = __float2half_rn(v - __half2float(h));
}

#define CP_ASYNC16(dst, src) \
    asm volatile("cp.async.cg.shared.global [%0], [%1], 16;" :: "r"(dst), "l"(src) : "memory")
#define CP_COMMIT() asm volatile("cp.async.commit_group;" ::: "memory")
#define CP_WAIT1()  asm volatile("cp.async.wait_group 1;" ::: "memory")

#define LDSM_X4(r, a)                                                        \
    asm volatile("ldmatrix.sync.aligned.m8n8.x4.shared.b16 {%0,%1,%2,%3}, [%4];" \
        : "=r"((r)[0]), "=r"((r)[1]), "=r"((r)[2]), "=r"((r)[3]) : "r"(a))

__device__ __forceinline__ void mma_f16(float* c, const uint32_t* a,
                                        uint32_t b0, uint32_t b1) {
    asm volatile(
        "mma.sync.aligned.m16n8k16.row.col.f32.f16.f16.f32 "
        "{%0,%1,%2,%3}, {%4,%5,%6,%7}, {%8,%9}, {%0,%1,%2,%3};"
        : "+f"(c[0]), "+f"(c[1]), "+f"(c[2]), "+f"(c[3])
        : "r"(a[0]), "r"(a[1]), "r"(a[2]), "r"(a[3]), "r"(b0), "r"(b1));
}

// ---------------- embed (+split) ----------------
__global__ void embed_split(const int* __restrict__ tokens, const float* __restrict__ emb,
                            float* __restrict__ x, h16* __restrict__ xh, h16* __restrict__ xl) {
    int i = blockIdx.x;
    int tok = tokens[i];
    const float4* src = (const float4*)(emb + (long)tok * HDIM);
    float4* dst = (float4*)(x + (long)i * HDIM);
    for (int c = threadIdx.x; c < HDIM / 4; c += blockDim.x) {
        float4 v = src[c];
        dst[c] = v;
        h16 h0, l0, h1, l1, h2, l2, h3, l3;
        split1(v.x, h0, l0); split1(v.y, h1, l1);
        split1(v.z, h2, l2); split1(v.w, h3, l3);
        long base = (long)i * HDIM + c * 4;
        *(__half2*)(xh + base)     = __halves2half2(h0, h1);
        *(__half2*)(xh + base + 2) = __halves2half2(h2, h3);
        *(__half2*)(xl + base)     = __halves2half2(l0, l1);
        *(__half2*)(xl + base + 2) = __halves2half2(l2, l3);
    }
}

// ---------------- transpose -> single fp16 (batched) ----------------
__global__ void transpose_f16(const float* __restrict__ src, h16* __restrict__ dst,
                              int R, int lds, long sbatch, long dbatch) {
    __shared__ float t[32][33];
    src += (long)blockIdx.z * sbatch;
    dst += (long)blockIdx.z * dbatch;
    int c0 = blockIdx.x << 5, r0 = blockIdx.y << 5;
    int x = threadIdx.x, y = threadIdx.y;
    #pragma unroll
    for (int i = y; i < 32; i += 8)
        t[i][x] = src[(long)(r0 + i) * lds + c0 + x];
    __syncthreads();
    #pragma unroll
    for (int j = y; j < 32; j += 8)
        dst[(long)(c0 + j) * R + r0 + x] = __float2half_rn(t[x][j]);
}

// ---------------- causal softmax -> fp16 (single) ----------------
__global__ void softmax_f16(float* __restrict__ sc, h16* __restrict__ sh, float scale) {
    int row = blockIdx.x;
    int s = row & (SEQ - 1);
    float* p = sc + (long)row * SEQ;
    h16* ph = sh + (long)row * SEQ;
    int tid = threadIdx.x;
    __shared__ float red[256];

    float m = -INFINITY;
    for (int t = tid; t <= s; t += blockDim.x) m = fmaxf(m, p[t] * scale);
    red[tid] = m; __syncthreads();
    for (int o = 128; o > 0; o >>= 1) {
        if (tid < o) red[tid] = fmaxf(red[tid], red[tid + o]);
        __syncthreads();
    }
    m = red[0]; __syncthreads();

    float sum = 0.f;
    for (int t = tid; t <= s; t += blockDim.x) {
        float e = __expf(p[t] * scale - m);
        p[t] = e;
        sum += e;
    }
    red[tid] = sum; __syncthreads();
    for (int o = 128; o > 0; o >>= 1) {
        if (tid < o) red[tid] += red[tid + o];
        __syncthreads();
    }
    float inv = 1.f / red[0];
    const h16 z = __float2half(0.f);
    for (int t = tid; t <= s; t += blockDim.x)
        ph[t] = __float2half_rn(p[t] * inv);
    for (int t = s + 1 + tid; t < SEQ; t += blockDim.x) ph[t] = z;
}

// ---------------- HMMA GEMM: C = (Ah [+Al]) @ Bh^T --------------------------
// CTA tile 128x256x32, 256 threads, 8 warps (2 M x 4 N), 64x64 warp tiles.
// PASSES=2: A exact fp16 hi/lo.  PASSES=1: A single fp16 (Al unused).
// EPI: 0 none, 1 +=Cf, 2 relu(+bias), 3 +bias+Cf, 4 +bias
// CSKIP: skip blocks with n0 > m0+127.  CK: truncate K loop at m0+128.
#define DEPTH     3
#define MAT_A     10240u                  // 128 rows * 80B
#define MAT_B     20480u                  // 256 rows * 80B
#define STG_BYTES 40960u                  // 2*MAT_A + MAT_B
#define SMEM_TOT  (DEPTH * STG_BYTES)     // 122880

template<int EPI, bool F32OUT, bool SPLITOUT, bool CSKIP, bool CK, int PASSES>
__global__ __launch_bounds__(256, 1)
void mma_gemm(const h16* __restrict__ Ah, const h16* __restrict__ Al,
              const h16* __restrict__ Bh,
              float* __restrict__ Cf, h16* __restrict__ Ch, h16* __restrict__ Cl,
              const float* __restrict__ bias,
              int K, int lda, int ldb, int ldc,
              long bsA, long bsB, long bsC) {
    const int m0 = blockIdx.y << 7;
    const int n0 = blockIdx.x << 8;
    if (CSKIP && n0 > m0 + 127) return;

    const long zA = (long)blockIdx.z * bsA;
    const long zB = (long)blockIdx.z * bsB;
    const long zC = (long)blockIdx.z * bsC;

    extern __shared__ char smem[];
    const uint32_t sbase = smem_u32(smem);
    const int tid = threadIdx.x;
    const int lane = tid & 31, wid = tid >> 5;
    const int wm = wid & 1, wn = wid >> 1;
    int NK = K >> 5;
    if (CK) { int nke = (m0 + 128) >> 5; NK = (nke < NK) ? nke : NK; }

    const h16* gm[3] = { Ah + zA + (long)m0 * lda, Al + zA + (long)m0 * lda,
                         Bh + zB + (long)n0 * ldb };
    const int  ldm[3]  = { lda, lda, ldb };
    const uint32_t moff[3] = { 0u, MAT_A, 2u * MAT_A };
    const int rgrp = tid >> 2;        // 0..63
    const int atom = tid & 3;
    constexpr int NROWI = (PASSES == 2) ? 8 : 6;

    float acc[4][8][4];
    #pragma unroll
    for (int a = 0; a < 4; a++)
        #pragma unroll
        for (int b = 0; b < 8; b++)
            #pragma unroll
            for (int c = 0; c < 4; c++) acc[a][b][c] = 0.f;

    // PASSES=2: i=0,1 -> A_h ; i=2,3 -> A_l ; i=4..7 -> B_h (256 rows)
    // PASSES=1: i=0,1 -> A_h ; i=2..5 -> B_h
    #define LOAD_STAGE(kt, slot) do {                                          \
        uint32_t st_ = sbase + (slot) * STG_BYTES;                             \
        _Pragma("unroll")                                                      \
        for (int i = 0; i < NROWI; i++) {                                      \
            int mat, lr;                                                       \
            if (PASSES == 2) {                                                 \
                mat = (i < 2) ? 0 : (i < 4) ? 1 : 2;                           \
                lr  = (i - ((mat == 0) ? 0 : (mat == 1) ? 2 : 4)) * 64 + rgrp; \
            } else {                                                           \
                mat = (i < 2) ? 0 : 2;                                         \
                lr  = (i - ((mat == 0) ? 0 : 2)) * 64 + rgrp;                  \
            }                                                                  \
            const h16* g = gm[mat] + (long)lr * ldm[mat] + ((kt) << 5) + (atom << 3); \
            CP_ASYNC16(st_ + moff[mat] + (uint32_t)lr * 80u + (atom << 4), g); \
        }                                                                      \
        CP_COMMIT();                                                           \
    } while (0)

    LOAD_STAGE(0, 0);
    LOAD_STAGE(1, 1);

    for (int kt = 0; kt < NK; kt++) {
        CP_WAIT1();
        __syncthreads();
        if (kt + 2 < NK) { LOAD_STAGE(kt + 2, (kt + 2) % DEPTH); }
        else             { CP_COMMIT(); }

        uint32_t st = sbase + (kt % DEPTH) * STG_BYTES;
        #pragma unroll
        for (int s = 0; s < 2; s++) {
            uint32_t a_h[4][4], a_l[4][4];
            #pragma unroll
            for (int mt = 0; mt < 4; mt++) {
                uint32_t ad = st + (uint32_t)(wm * 64 + mt * 16 + (lane & 15)) * 80u
                              + s * 32 + ((lane >> 4) << 4);
                LDSM_X4(a_h[mt], ad);
                if (PASSES == 2) LDSM_X4(a_l[mt], ad + MAT_A);
            }
            #pragma unroll
            for (int p = 0; p < 4; p++) {
                uint32_t b_h[4];
                uint32_t bd = st + 2u * MAT_A
                              + (uint32_t)(wn * 64 + p * 16 + ((lane >> 4) << 3) + (lane & 7)) * 80u
                              + s * 32 + (((lane >> 3) & 1) << 4);
                LDSM_X4(b_h, bd);
                #pragma unroll
                for (int q = 0; q < 2; q++) {
                    const int nt = p * 2 + q;
                    uint32_t bh0 = b_h[q * 2], bh1 = b_h[q * 2 + 1];
                    #pragma unroll
                    for (int mt = 0; mt < 4; mt++) {
                        mma_f16(acc[mt][nt], a_h[mt], bh0, bh1);
                        if (PASSES == 2) mma_f16(acc[mt][nt], a_l[mt], bh0, bh1);
                    }
                }
            }
        }
    }

    // ---- epilogue ----
    #pragma unroll
    for (int mt = 0; mt < 4; mt++) {
        #pragma unroll
        for (int nt = 0; nt < 8; nt++) {
            int mbase = m0 + wm * 64 + mt * 16 + (lane >> 2);
            int n = n0 + wn * 64 + nt * 8 + (lane & 3) * 2;
            #pragma unroll
            for (int hf = 0; hf < 2; hf++) {
                int mm = mbase + hf * 8;
                float vx = acc[mt][nt][hf * 2 + 0];
                float vy = acc[mt][nt][hf * 2 + 1];
                long idx = zC + (long)mm * ldc + n;
                if (EPI >= 2) { vx += bias[n]; vy += bias[n + 1]; }
                if (EPI == 2) { vx = fmaxf(vx, 0.f); vy = fmaxf(vy, 0.f); }
                if (EPI == 1 || EPI == 3) {
                    float2 old = *(const float2*)(Cf + idx);
                    vx += old.x; vy += old.y;
                }
                if (F32OUT) {
                    float2 o; o.x = vx; o.y = vy;
                    *(float2*)(Cf + idx) = o;
                }
                if (SPLITOUT) {
                    h16 hx, lx, hy, ly;
                    split1(vx, hx, lx); split1(vy, hy, ly);
                    *(__half2*)(Ch + idx) = __halves2half2(hx, hy);
                    *(__half2*)(Cl + idx) = __halves2half2(lx, ly);
                }
            }
        }
    }
}

// ---------------- host ----------------
template<int EPI, bool F32O, bool SPL, bool CSKIP = false, bool CK = false, int PASSES = 2>
static void launch_mma(dim3 grid, const h16* Ah, const h16* Al, const h16* Bh,
                       float* Cf, h16* Ch, h16* Cl, const float* bias,
                       int K, int lda, int ldb, int ldc,
                       long bsA = 0, long bsB = 0, long bsC = 0) {
    cudaFuncSetAttribute(mma_gemm<EPI, F32O, SPL, CSKIP, CK, PASSES>,
                         cudaFuncAttributeMaxDynamicSharedMemorySize, SMEM_TOT);
    mma_gemm<EPI, F32O, SPL, CSKIP, CK, PASSES><<<grid, 256, SMEM_TOT>>>(
        Ah, Al, Bh, Cf, Ch, Cl, bias, K, lda, ldb, ldc, bsA, bsB, bsC);
}

#define SYM(p, g) cudaGetSymbolAddress((void**)&p, g)

extern "C" void kernel_launch(void* const* d_in, const int* in_sizes, int n_in,
                              void* d_out, int out_size) {
    const int*   tokens    = (const int*)  d_in[0];
    const float* embedding = (const float*)d_in[1];
    const float* qkv_w     = (const float*)d_in[2];
    const float* o_w       = (const float*)d_in[3];
    const float* up_w      = (const float*)d_in[4];
    const float* up_b      = (const float*)d_in[5];
    const float* down_w    = (const float*)d_in[6];
    const float* down_b    = (const float*)d_in[7];
    const float* unemb_w   = (const float*)d_in[8];
    const float* unemb_b   = (const float*)d_in[9];
    float* logits = (float*)d_out;

    float *x, *qkv, *sc;
    h16 *xh, *xl, *qh, *ql, *sh, *vTh, *oh, *ol, *hh, *hl;
    h16 *qkvT, *oT, *upT, *dnT, *unT;
    SYM(x, g_x); SYM(qkv, g_qkv); SYM(sc, g_scores);
    SYM(xh, g_xh); SYM(xl, g_xl);
    SYM(qh, g_qkvh); SYM(ql, g_qkvl);
    SYM(sh, g_sh);
    SYM(vTh, g_vTh);
    SYM(oh, g_oh); SYM(ol, g_ol);
    SYM(hh, g_hh); SYM(hl, g_hl);
    SYM(qkvT, g_qkvT); SYM(oT, g_oT); SYM(upT, g_upT); SYM(dnT, g_dnT); SYM(unT, g_unT);

    const float scale = 1.0f / sqrtf((float)KDIM);
    dim3 tb(32, 8);

    // weight transposes -> [N,K] single fp16
    transpose_f16<<<dim3(3 * KDIM / 32, HDIM / 32, LAYERS), tb>>>(
        qkv_w, qkvT, HDIM, 3 * KDIM, (long)HDIM * 3 * KDIM, (long)HDIM * 3 * KDIM);
    transpose_f16<<<dim3(HDIM / 32, KDIM / 32, LAYERS), tb>>>(
        o_w, oT, KDIM, HDIM, (long)KDIM * HDIM, (long)KDIM * HDIM);
    transpose_f16<<<dim3(IDIM / 32, HDIM / 32, LAYERS), tb>>>(
        up_w, upT, HDIM, IDIM, (long)HDIM * IDIM, (long)HDIM * IDIM);
    transpose_f16<<<dim3(HDIM / 32, IDIM / 32, LAYERS), tb>>>(
        down_w, dnT, IDIM, HDIM, (long)IDIM * HDIM, (long)IDIM * HDIM);
    transpose_f16<<<dim3(VOCAB / 32, HDIM / 32, 1), tb>>>(
        unemb_w, unT, HDIM, VOCAB, 0, 0);

    embed_split<<<MTOK, 256>>>(tokens, embedding, x, xh, xl);

    for (int l = 0; l < LAYERS; l++) {
        h16* wq = qkvT + (long)l * 3 * KDIM * HDIM;
        h16* wo = oT   + (long)l * HDIM * KDIM;
        h16* wu = upT  + (long)l * IDIM * HDIM;
        h16* wd = dnT  + (long)l * HDIM * IDIM;
        const float* bu = up_b   + (long)l * IDIM;
        const float* bd = down_b + (long)l * HDIM;

        // qkv = x @ Wqkv (2-pass) -> fp32 (for V transpose) + split
        launch_mma<0, true, true>(dim3(3 * KDIM / 256, MTOK / 128, 1),
            xh, xl, wq, qkv, qh, ql, nullptr, HDIM, HDIM, HDIM, 3 * KDIM);

        // vT[b][k][t] = fp16(V[b][t][k])
        transpose_f16<<<dim3(KDIM / 32, SEQ / 32, BATCH), tb>>>(
            qkv + 2 * KDIM, vTh, SEQ, 3 * KDIM,
            (long)SEQ * 3 * KDIM, (long)KDIM * SEQ);

        // scores = Q @ K^T (1-pass; causal block skip)
        launch_mma<0, true, false, true, false, 1>(dim3(SEQ / 256, SEQ / 128, BATCH),
            qh, qh, qh + KDIM, sc, nullptr, nullptr, nullptr,
            KDIM, 3 * KDIM, 3 * KDIM, SEQ,
            (long)SEQ * 3 * KDIM, (long)SEQ * 3 * KDIM, (long)SEQ * SEQ);

        softmax_f16<<<BATCH * SEQ, 256>>>(sc, sh, scale);

        // o = attn @ V (1-pass; K truncated at diagonal)
        launch_mma<0, false, true, false, true, 1>(dim3(KDIM / 256, SEQ / 128, BATCH),
            sh, sh, vTh, nullptr, oh, ol, nullptr,
            SEQ, SEQ, SEQ, KDIM,
            (long)SEQ * SEQ, (long)KDIM * SEQ, (long)SEQ * KDIM);

        // x += o @ Wo (2-pass)
        launch_mma<1, true, true>(dim3(HDIM / 256, MTOK / 128, 1),
            oh, ol, wo, x, xh, xl, nullptr, KDIM, KDIM, KDIM, HDIM);

        // h = relu(x @ Wu + bu) (1-pass: A = xh only)
        launch_mma<2, false, true, false, false, 1>(dim3(IDIM / 256, MTOK / 128, 1),
            xh, xh, wu, nullptr, hh, hl, bu, HDIM, HDIM, HDIM, IDIM);

        // x += h @ Wd + bd (2-pass)
        launch_mma<3, true, true>(dim3(HDIM / 256, MTOK / 128, 1),
            hh, hl, wd, x, xh, xl, bd, IDIM, IDIM, IDIM, HDIM);
    }

    // logits = x @ Wun + b (1-pass: A = xh only)
    launch_mma<4, true, false, false, false, 1>(dim3(VOCAB / 256, MTOK / 128, 1),
        xh, xh, unT, logits, nullptr, nullptr, unemb_b,
        HDIM, HDIM, HDIM, VOCAB);
}

// round 13
// speedup vs baseline: 5.4364x; 1.2706x over previous
#include <cuda_runtime.h>
#include <cuda_fp16.h>
#include <math.h>
#include <stdint.h>

#define LAYERS 8
#define HDIM   1024
#define KDIM   1024
#define IDIM   4096
#define VOCAB  32000
#define BATCH  2
#define SEQ    2048
#define MTOK   (BATCH * SEQ)

typedef __half h16;

// ---------------- scratch (device globals) ----------------
__device__ float g_x[(long)MTOK * HDIM];
__device__ float g_qkv[(long)MTOK * 3 * KDIM];
__device__ float g_scores[(long)BATCH * SEQ * SEQ];
__device__ h16 g_xh[(long)MTOK * HDIM];
__device__ h16 g_qkvh[(long)MTOK * 3 * KDIM];
__device__ h16 g_sh[(long)BATCH * SEQ * SEQ];
__device__ h16 g_vTh[(long)BATCH * KDIM * SEQ];
__device__ h16 g_oh[(long)MTOK * KDIM];
__device__ h16 g_hh[(long)MTOK * IDIM];
// single-fp16 transposed weights [N,K]
__device__ h16 g_qkvT[(long)LAYERS * 3 * KDIM * HDIM];
__device__ h16 g_oT[(long)LAYERS * HDIM * KDIM];
__device__ h16 g_upT[(long)LAYERS * IDIM * HDIM];
__device__ h16 g_dnT[(long)LAYERS * HDIM * IDIM];
__device__ h16 g_unT[(long)VOCAB * HDIM];

// ---------------- helpers ----------------
__device__ __forceinline__ uint32_t smem_u32(const void* p) {
    uint32_t a;
    asm("{ .reg .u64 t; cvta.to.shared.u64 t, %1; cvt.u32.u64 %0, t; }" : "=r"(a) : "l"(p));
    return a;
}

#define CP_ASYNC16(dst, src) \
    asm volatile("cp.async.cg.shared.global [%0], [%1], 16;" :: "r"(dst), "l"(src) : "memory")
#define CP_COMMIT() asm volatile("cp.async.commit_group;" ::: "memory")
#define CP_WAIT1()  asm volatile("cp.async.wait_group 1;" ::: "memory")

#define LDSM_X4(r, a)                                                        \
    asm volatile("ldmatrix.sync.aligned.m8n8.x4.shared.b16 {%0,%1,%2,%3}, [%4];" \
        : "=r"((r)[0]), "=r"((r)[1]), "=r"((r)[2]), "=r"((r)[3]) : "r"(a))

__device__ __forceinline__ void mma_f16(float* c, const uint32_t* a,
                                        uint32_t b0, uint32_t b1) {
    asm volatile(
        "mma.sync.aligned.m16n8k16.row.col.f32.f16.f16.f32 "
        "{%0,%1,%2,%3}, {%4,%5,%6,%7}, {%8,%9}, {%0,%1,%2,%3};"
        : "+f"(c[0]), "+f"(c[1]), "+f"(c[2]), "+f"(c[3])
        : "r"(a[0]), "r"(a[1]), "r"(a[2]), "r"(a[3]), "r"(b0), "r"(b1));
}

// ---------------- embed (+fp16 copy) ----------------
__global__ void embed_f16(const int* __restrict__ tokens, const float* __restrict__ emb,
                          float* __restrict__ x, h16* __restrict__ xh) {
    int i = blockIdx.x;
    int tok = tokens[i];
    const float4* src = (const float4*)(emb + (long)tok * HDIM);
    float4* dst = (float4*)(x + (long)i * HDIM);
    for (int c = threadIdx.x; c < HDIM / 4; c += blockDim.x) {
        float4 v = src[c];
        dst[c] = v;
        long base = (long)i * HDIM + c * 4;
        *(__half2*)(xh + base)     = __halves2half2(__float2half_rn(v.x), __float2half_rn(v.y));
        *(__half2*)(xh + base + 2) = __halves2half2(__float2half_rn(v.z), __float2half_rn(v.w));
    }
}

// ---------------- transpose -> single fp16 (batched) ----------------
__global__ void transpose_f16(const float* __restrict__ src, h16* __restrict__ dst,
                              int R, int lds, long sbatch, long dbatch) {
    __shared__ float t[32][33];
    src += (long)blockIdx.z * sbatch;
    dst += (long)blockIdx.z * dbatch;
    int c0 = blockIdx.x << 5, r0 = blockIdx.y << 5;
    int x = threadIdx.x, y = threadIdx.y;
    #pragma unroll
    for (int i = y; i < 32; i += 8)
        t[i][x] = src[(long)(r0 + i) * lds + c0 + x];
    __syncthreads();
    #pragma unroll
    for (int j = y; j < 32; j += 8)
        dst[(long)(c0 + j) * R + r0 + x] = __float2half_rn(t[x][j]);
}

// ---------------- causal softmax -> fp16 ----------------
__global__ void softmax_f16(float* __restrict__ sc, h16* __restrict__ sh, float scale) {
    int row = blockIdx.x;
    int s = row & (SEQ - 1);
    float* p = sc + (long)row * SEQ;
    h16* ph = sh + (long)row * SEQ;
    int tid = threadIdx.x;
    __shared__ float red[256];

    float m = -INFINITY;
    for (int t = tid; t <= s; t += blockDim.x) m = fmaxf(m, p[t] * scale);
    red[tid] = m; __syncthreads();
    for (int o = 128; o > 0; o >>= 1) {
        if (tid < o) red[tid] = fmaxf(red[tid], red[tid + o]);
        __syncthreads();
    }
    m = red[0]; __syncthreads();

    float sum = 0.f;
    for (int t = tid; t <= s; t += blockDim.x) {
        float e = __expf(p[t] * scale - m);
        p[t] = e;
        sum += e;
    }
    red[tid] = sum; __syncthreads();
    for (int o = 128; o > 0; o >>= 1) {
        if (tid < o) red[tid] += red[tid + o];
        __syncthreads();
    }
    float inv = 1.f / red[0];
    const h16 z = __float2half(0.f);
    for (int t = tid; t <= s; t += blockDim.x)
        ph[t] = __float2half_rn(p[t] * inv);
    for (int t = s + 1 + tid; t < SEQ; t += blockDim.x) ph[t] = z;
}

// ---------------- 1-pass HMMA GEMM: C = A @ B^T (both fp16) ----------------
// CTA tile 128x256x32, 256 threads, 8 warps (2 M x 4 N), 64x64 warp tiles.
// EPI: 0 none, 1 +=Cf, 2 relu(+bias), 3 +bias+Cf, 4 +bias
// F32OUT: write Cf (fp32).  F16OUT: write Ch (fp16).
// CSKIP: skip blocks with n0 > m0+127.  CK: truncate K loop at m0+128.
#define DEPTH     3
#define MAT_A     10240u                  // 128 rows * 80B
#define MAT_B     20480u                  // 256 rows * 80B
#define STG_BYTES 30720u                  // MAT_A + MAT_B
#define SMEM_TOT  (DEPTH * STG_BYTES)     // 92160

template<int EPI, bool F32OUT, bool F16OUT, bool CSKIP, bool CK>
__global__ __launch_bounds__(256, 1)
void mma_gemm(const h16* __restrict__ Ah, const h16* __restrict__ Bh,
              float* __restrict__ Cf, h16* __restrict__ Ch,
              const float* __restrict__ bias,
              int K, int lda, int ldb, int ldc,
              long bsA, long bsB, long bsC) {
    const int m0 = blockIdx.y << 7;
    const int n0 = blockIdx.x << 8;
    if (CSKIP && n0 > m0 + 127) return;

    const long zA = (long)blockIdx.z * bsA;
    const long zB = (long)blockIdx.z * bsB;
    const long zC = (long)blockIdx.z * bsC;

    extern __shared__ char smem[];
    const uint32_t sbase = smem_u32(smem);
    const int tid = threadIdx.x;
    const int lane = tid & 31, wid = tid >> 5;
    const int wm = wid & 1, wn = wid >> 1;
    int NK = K >> 5;
    if (CK) { int nke = (m0 + 128) >> 5; NK = (nke < NK) ? nke : NK; }

    const h16* gA = Ah + zA + (long)m0 * lda;
    const h16* gB = Bh + zB + (long)n0 * ldb;
    const int rgrp = tid >> 2;        // 0..63
    const int atom = tid & 3;

    float acc[4][8][4];
    #pragma unroll
    for (int a = 0; a < 4; a++)
        #pragma unroll
        for (int b = 0; b < 8; b++)
            #pragma unroll
            for (int c = 0; c < 4; c++) acc[a][b][c] = 0.f;

    // i=0,1 -> A rows 0..127 ; i=2..5 -> B rows 0..255
    #define LOAD_STAGE(kt, slot) do {                                          \
        uint32_t st_ = sbase + (slot) * STG_BYTES;                             \
        _Pragma("unroll")                                                      \
        for (int i = 0; i < 6; i++) {                                          \
            const bool isA = (i < 2);                                          \
            const int lr = (isA ? i : (i - 2)) * 64 + rgrp;                    \
            const h16* g = (isA ? gA + (long)lr * lda : gB + (long)lr * ldb)   \
                           + ((kt) << 5) + (atom << 3);                        \
            CP_ASYNC16(st_ + (isA ? 0u : MAT_A) + (uint32_t)lr * 80u + (atom << 4), g); \
        }                                                                      \
        CP_COMMIT();                                                           \
    } while (0)

    LOAD_STAGE(0, 0);
    LOAD_STAGE(1, 1);

    for (int kt = 0; kt < NK; kt++) {
        CP_WAIT1();
        __syncthreads();
        if (kt + 2 < NK) { LOAD_STAGE(kt + 2, (kt + 2) % DEPTH); }
        else             { CP_COMMIT(); }

        uint32_t st = sbase + (kt % DEPTH) * STG_BYTES;
        #pragma unroll
        for (int s = 0; s < 2; s++) {
            uint32_t a_h[4][4];
            #pragma unroll
            for (int mt = 0; mt < 4; mt++) {
                uint32_t ad = st + (uint32_t)(wm * 64 + mt * 16 + (lane & 15)) * 80u
                              + s * 32 + ((lane >> 4) << 4);
                LDSM_X4(a_h[mt], ad);
            }
            #pragma unroll
            for (int p = 0; p < 4; p++) {
                uint32_t b_h[4];
                uint32_t bd = st + MAT_A
                              + (uint32_t)(wn * 64 + p * 16 + ((lane >> 4) << 3) + (lane & 7)) * 80u
                              + s * 32 + (((lane >> 3) & 1) << 4);
                LDSM_X4(b_h, bd);
                #pragma unroll
                for (int q = 0; q < 2; q++) {
                    const int nt = p * 2 + q;
                    uint32_t bh0 = b_h[q * 2], bh1 = b_h[q * 2 + 1];
                    #pragma unroll
                    for (int mt = 0; mt < 4; mt++)
                        mma_f16(acc[mt][nt], a_h[mt], bh0, bh1);
                }
            }
        }
    }

    // ---- epilogue ----
    #pragma unroll
    for (int mt = 0; mt < 4; mt++) {
        #pragma unroll
        for (int nt = 0; nt < 8; nt++) {
            int mbase = m0 + wm * 64 + mt * 16 + (lane >> 2);
            int n = n0 + wn * 64 + nt * 8 + (lane & 3) * 2;
            #pragma unroll
            for (int hf = 0; hf < 2; hf++) {
                int mm = mbase + hf * 8;
                float vx = acc[mt][nt][hf * 2 + 0];
                float vy = acc[mt][nt][hf * 2 + 1];
                long idx = zC + (long)mm * ldc + n;
                if (EPI >= 2) { vx += bias[n]; vy += bias[n + 1]; }
                if (EPI == 2) { vx = fmaxf(vx, 0.f); vy = fmaxf(vy, 0.f); }
                if (EPI == 1 || EPI == 3) {
                    float2 old = *(const float2*)(Cf + idx);
                    vx += old.x; vy += old.y;
                }
                if (F32OUT) {
                    float2 o; o.x = vx; o.y = vy;
                    *(float2*)(Cf + idx) = o;
                }
                if (F16OUT) {
                    *(__half2*)(Ch + idx) =
                        __halves2half2(__float2half_rn(vx), __float2half_rn(vy));
                }
            }
        }
    }
}

// ---------------- host ----------------
template<int EPI, bool F32O, bool F16O, bool CSKIP = false, bool CK = false>
static void launch_mma(dim3 grid, const h16* Ah, const h16* Bh,
                       float* Cf, h16* Ch, const float* bias,
                       int K, int lda, int ldb, int ldc,
                       long bsA = 0, long bsB = 0, long bsC = 0) {
    cudaFuncSetAttribute(mma_gemm<EPI, F32O, F16O, CSKIP, CK>,
                         cudaFuncAttributeMaxDynamicSharedMemorySize, SMEM_TOT);
    mma_gemm<EPI, F32O, F16O, CSKIP, CK><<<grid, 256, SMEM_TOT>>>(
        Ah, Bh, Cf, Ch, bias, K, lda, ldb, ldc, bsA, bsB, bsC);
}

#define SYM(p, g) cudaGetSymbolAddress((void**)&p, g)

extern "C" void kernel_launch(void* const* d_in, const int* in_sizes, int n_in,
                              void* d_out, int out_size) {
    const int*   tokens    = (const int*)  d_in[0];
    const float* embedding = (const float*)d_in[1];
    const float* qkv_w     = (const float*)d_in[2];
    const float* o_w       = (const float*)d_in[3];
    const float* up_w      = (const float*)d_in[4];
    const float* up_b      = (const float*)d_in[5];
    const float* down_w    = (const float*)d_in[6];
    const float* down_b    = (const float*)d_in[7];
    const float* unemb_w   = (const float*)d_in[8];
    const float* unemb_b   = (const float*)d_in[9];
    float* logits = (float*)d_out;

    float *x, *qkv, *sc;
    h16 *xh, *qh, *sh, *vTh, *oh, *hh;
    h16 *qkvT, *oT, *upT, *dnT, *unT;
    SYM(x, g_x); SYM(qkv, g_qkv); SYM(sc, g_scores);
    SYM(xh, g_xh);
    SYM(qh, g_qkvh);
    SYM(sh, g_sh);
    SYM(vTh, g_vTh);
    SYM(oh, g_oh);
    SYM(hh, g_hh);
    SYM(qkvT, g_qkvT); SYM(oT, g_oT); SYM(upT, g_upT); SYM(dnT, g_dnT); SYM(unT, g_unT);

    const float scale = 1.0f / sqrtf((float)KDIM);
    dim3 tb(32, 8);

    // weight transposes -> [N,K] single fp16
    transpose_f16<<<dim3(3 * KDIM / 32, HDIM / 32, LAYERS), tb>>>(
        qkv_w, qkvT, HDIM, 3 * KDIM, (long)HDIM * 3 * KDIM, (long)HDIM * 3 * KDIM);
    transpose_f16<<<dim3(HDIM / 32, KDIM / 32, LAYERS), tb>>>(
        o_w, oT, KDIM, HDIM, (long)KDIM * HDIM, (long)KDIM * HDIM);
    transpose_f16<<<dim3(IDIM / 32, HDIM / 32, LAYERS), tb>>>(
        up_w, upT, HDIM, IDIM, (long)HDIM * IDIM, (long)HDIM * IDIM);
    transpose_f16<<<dim3(HDIM / 32, IDIM / 32, LAYERS), tb>>>(
        down_w, dnT, IDIM, HDIM, (long)IDIM * HDIM, (long)IDIM * HDIM);
    transpose_f16<<<dim3(VOCAB / 32, HDIM / 32, 1), tb>>>(
        unemb_w, unT, HDIM, VOCAB, 0, 0);

    embed_f16<<<MTOK, 256>>>(tokens, embedding, x, xh);

    for (int l = 0; l < LAYERS; l++) {
        h16* wq = qkvT + (long)l * 3 * KDIM * HDIM;
        h16* wo = oT   + (long)l * HDIM * KDIM;
        h16* wu = upT  + (long)l * IDIM * HDIM;
        h16* wd = dnT  + (long)l * HDIM * IDIM;
        const float* bu = up_b   + (long)l * IDIM;
        const float* bd = down_b + (long)l * HDIM;

        // qkv = x @ Wqkv -> fp32 (for V transpose) + fp16 (Q,K operands)
        launch_mma<0, true, true>(dim3(3 * KDIM / 256, MTOK / 128, 1),
            xh, wq, qkv, qh, nullptr, HDIM, HDIM, HDIM, 3 * KDIM);

        // vT[b][k][t] = fp16(V[b][t][k])
        transpose_f16<<<dim3(KDIM / 32, SEQ / 32, BATCH), tb>>>(
            qkv + 2 * KDIM, vTh, SEQ, 3 * KDIM,
            (long)SEQ * 3 * KDIM, (long)KDIM * SEQ);

        // scores = Q @ K^T (causal block skip)
        launch_mma<0, true, false, true, false>(dim3(SEQ / 256, SEQ / 128, BATCH),
            qh, qh + KDIM, sc, nullptr, nullptr,
            KDIM, 3 * KDIM, 3 * KDIM, SEQ,
            (long)SEQ * 3 * KDIM, (long)SEQ * 3 * KDIM, (long)SEQ * SEQ);

        softmax_f16<<<BATCH * SEQ, 256>>>(sc, sh, scale);

        // o = attn @ V (K truncated at diagonal) -> fp16 only
        launch_mma<0, false, true, false, true>(dim3(KDIM / 256, SEQ / 128, BATCH),
            sh, vTh, nullptr, oh, nullptr,
            SEQ, SEQ, SEQ, KDIM,
            (long)SEQ * SEQ, (long)KDIM * SEQ, (long)SEQ * KDIM);

        // x += o @ Wo -> fp32 + fp16
        launch_mma<1, true, true>(dim3(HDIM / 256, MTOK / 128, 1),
            oh, wo, x, xh, nullptr, KDIM, KDIM, KDIM, HDIM);

        // h = relu(x @ Wu + bu) -> fp16 only
        launch_mma<2, false, true>(dim3(IDIM / 256, MTOK / 128, 1),
            xh, wu, nullptr, hh, bu, HDIM, HDIM, HDIM, IDIM);

        // x += h @ Wd + bd -> fp32 + fp16
        launch_mma<3, true, true>(dim3(HDIM / 256, MTOK / 128, 1),
            hh, wd, x, xh, bd, IDIM, IDIM, IDIM, HDIM);
    }

    // logits = x @ Wun + b
    launch_mma<4, true, false>(dim3(VOCAB / 256, MTOK / 128, 1),
        xh, unT, logits, nullptr, unemb_b,
        HDIM, HDIM, HDIM, VOCAB);
}

// round 14
// speedup vs baseline: 5.6431x; 1.0380x over previous
#include <cuda_runtime.h>
#include <cuda_fp16.h>
#include <math.h>
#include <stdint.h>

#define LAYERS 8
#define HDIM   1024
#define KDIM   1024
#define IDIM   4096
#define VOCAB  32000
#define BATCH  2
#define SEQ    2048
#define MTOK   (BATCH * SEQ)

typedef __half h16;

// ---------------- scratch (device globals) ----------------
__device__ float g_x[(long)MTOK * HDIM];
__device__ float g_scores[(long)BATCH * SEQ * SEQ];
__device__ h16 g_xh[(long)MTOK * HDIM];
__device__ h16 g_qkvh[(long)MTOK * 3 * KDIM];
__device__ h16 g_sh[(long)BATCH * SEQ * SEQ];
__device__ h16 g_vTh[(long)BATCH * KDIM * SEQ];
__device__ h16 g_oh[(long)MTOK * KDIM];
__device__ h16 g_hh[(long)MTOK * IDIM];
// single-fp16 transposed weights [N,K]
__device__ h16 g_qkvT[(long)LAYERS * 3 * KDIM * HDIM];
__device__ h16 g_oT[(long)LAYERS * HDIM * KDIM];
__device__ h16 g_upT[(long)LAYERS * IDIM * HDIM];
__device__ h16 g_dnT[(long)LAYERS * HDIM * IDIM];
__device__ h16 g_unT[(long)VOCAB * HDIM];

// ---------------- helpers ----------------
__device__ __forceinline__ uint32_t smem_u32(const void* p) {
    uint32_t a;
    asm("{ .reg .u64 t; cvta.to.shared.u64 t, %1; cvt.u32.u64 %0, t; }" : "=r"(a) : "l"(p));
    return a;
}

#define CP_ASYNC16(dst, src) \
    asm volatile("cp.async.cg.shared.global [%0], [%1], 16;" :: "r"(dst), "l"(src) : "memory")
#define CP_COMMIT() asm volatile("cp.async.commit_group;" ::: "memory")
#define CP_WAIT1()  asm volatile("cp.async.wait_group 1;" ::: "memory")

#define LDSM_X4(r, a)                                                        \
    asm volatile("ldmatrix.sync.aligned.m8n8.x4.shared.b16 {%0,%1,%2,%3}, [%4];" \
        : "=r"((r)[0]), "=r"((r)[1]), "=r"((r)[2]), "=r"((r)[3]) : "r"(a))

__device__ __forceinline__ void mma_f16(float* c, const uint32_t* a,
                                        uint32_t b0, uint32_t b1) {
    asm volatile(
        "mma.sync.aligned.m16n8k16.row.col.f32.f16.f16.f32 "
        "{%0,%1,%2,%3}, {%4,%5,%6,%7}, {%8,%9}, {%0,%1,%2,%3};"
        : "+f"(c[0]), "+f"(c[1]), "+f"(c[2]), "+f"(c[3])
        : "r"(a[0]), "r"(a[1]), "r"(a[2]), "r"(a[3]), "r"(b0), "r"(b1));
}

// ---------------- embed (+fp16 copy) ----------------
__global__ void embed_f16(const int* __restrict__ tokens, const float* __restrict__ emb,
                          float* __restrict__ x, h16* __restrict__ xh) {
    int i = blockIdx.x;
    int tok = tokens[i];
    const float4* src = (const float4*)(emb + (long)tok * HDIM);
    float4* dst = (float4*)(x + (long)i * HDIM);
    for (int c = threadIdx.x; c < HDIM / 4; c += blockDim.x) {
        float4 v = src[c];
        dst[c] = v;
        long base = (long)i * HDIM + c * 4;
        *(__half2*)(xh + base)     = __halves2half2(__float2half_rn(v.x), __float2half_rn(v.y));
        *(__half2*)(xh + base + 2) = __halves2half2(__float2half_rn(v.z), __float2half_rn(v.w));
    }
}

// ---------------- transpose fp32 -> fp16 (batched) ----------------
__global__ void transpose_f16(const float* __restrict__ src, h16* __restrict__ dst,
                              int R, int lds, long sbatch, long dbatch) {
    __shared__ float t[32][33];
    src += (long)blockIdx.z * sbatch;
    dst += (long)blockIdx.z * dbatch;
    int c0 = blockIdx.x << 5, r0 = blockIdx.y << 5;
    int x = threadIdx.x, y = threadIdx.y;
    #pragma unroll
    for (int i = y; i < 32; i += 8)
        t[i][x] = src[(long)(r0 + i) * lds + c0 + x];
    __syncthreads();
    #pragma unroll
    for (int j = y; j < 32; j += 8)
        dst[(long)(c0 + j) * R + r0 + x] = __float2half_rn(t[x][j]);
}

// ---------------- transpose fp16 -> fp16 (batched, for V) ----------------
__global__ void transpose_h16(const h16* __restrict__ src, h16* __restrict__ dst,
                              int R, int lds, long sbatch, long dbatch) {
    __shared__ h16 t[32][33];
    src += (long)blockIdx.z * sbatch;
    dst += (long)blockIdx.z * dbatch;
    int c0 = blockIdx.x << 5, r0 = blockIdx.y << 5;
    int x = threadIdx.x, y = threadIdx.y;
    #pragma unroll
    for (int i = y; i < 32; i += 8)
        t[i][x] = src[(long)(r0 + i) * lds + c0 + x];
    __syncthreads();
    #pragma unroll
    for (int j = y; j < 32; j += 8)
        dst[(long)(c0 + j) * R + r0 + x] = t[x][j];
}

// ---------------- causal softmax -> fp16, balanced row pairs ---------------
__device__ __forceinline__ void softmax_row(float* __restrict__ sc,
                                            h16* __restrict__ sh,
                                            int b, int s, float scale,
                                            float* red) {
    float* p = sc + (long)(b * SEQ + s) * SEQ;
    h16* ph = sh + (long)(b * SEQ + s) * SEQ;
    int tid = threadIdx.x;

    float m = -INFINITY;
    for (int t = tid; t <= s; t += 256) m = fmaxf(m, p[t] * scale);
    red[tid] = m; __syncthreads();
    for (int o = 128; o > 0; o >>= 1) {
        if (tid < o) red[tid] = fmaxf(red[tid], red[tid + o]);
        __syncthreads();
    }
    m = red[0]; __syncthreads();

    float sum = 0.f;
    for (int t = tid; t <= s; t += 256) {
        float e = __expf(p[t] * scale - m);
        p[t] = e;
        sum += e;
    }
    red[tid] = sum; __syncthreads();
    for (int o = 128; o > 0; o >>= 1) {
        if (tid < o) red[tid] += red[tid + o];
        __syncthreads();
    }
    float inv = 1.f / red[0];
    __syncthreads();
    const h16 z = __float2half(0.f);
    for (int t = tid; t <= s; t += 256)
        ph[t] = __float2half_rn(p[t] * inv);
    for (int t = s + 1 + tid; t < SEQ; t += 256) ph[t] = z;
}

__global__ void softmax_pair(float* __restrict__ sc, h16* __restrict__ sh, float scale) {
    __shared__ float red[256];
    int pid = blockIdx.x;                 // 0 .. BATCH*SEQ/2-1
    int b = pid / (SEQ / 2);
    int sp = pid % (SEQ / 2);
    softmax_row(sc, sh, b, sp, scale, red);
    __syncthreads();
    softmax_row(sc, sh, b, SEQ - 1 - sp, scale, red);
}

// ---------------- 1-pass HMMA GEMM: C = A @ B^T (both fp16) ----------------
// CTA tile 128 x NT x 32 (NT = 128 or 256), 256 threads, 8 warps (2M x 4N).
// EPI: 0 none, 1 +=Cf, 2 relu(+bias), 3 +bias+Cf, 4 +bias
// F32OUT: write Cf.  F16OUT: write Ch.
// CSKIP: skip blocks with n0 > m0+127.
// CK: truncate K loop at m0+128 AND flip blockIdx.y (heavy tiles first).
#define DEPTH  3
#define MAT_A  10240u                     // 128 rows * 80B

template<int EPI, bool F32OUT, bool F16OUT, bool CSKIP, bool CK, int NT>
__global__ __launch_bounds__(256, 1)
void mma_gemm(const h16* __restrict__ Ah, const h16* __restrict__ Bh,
              float* __restrict__ Cf, h16* __restrict__ Ch,
              const float* __restrict__ bias,
              int K, int lda, int ldb, int ldc,
              long bsA, long bsB, long bsC) {
    constexpr uint32_t MATB = (uint32_t)NT * 80u;
    constexpr uint32_t STG  = MAT_A + MATB;
    constexpr int NB  = NT / 64;          // 64-row B groups per stage
    constexpr int NTI = NT / 32;          // 8-col acc tiles per warp

    const int my = CK ? (gridDim.y - 1 - blockIdx.y) : blockIdx.y;
    const int m0 = my << 7;
    const int n0 = blockIdx.x * NT;
    if (CSKIP && n0 > m0 + 127) return;

    const long zA = (long)blockIdx.z * bsA;
    const long zB = (long)blockIdx.z * bsB;
    const long zC = (long)blockIdx.z * bsC;

    extern __shared__ char smem[];
    const uint32_t sbase = smem_u32(smem);
    const int tid = threadIdx.x;
    const int lane = tid & 31, wid = tid >> 5;
    const int wm = wid & 1, wn = wid >> 1;
    int NK = K >> 5;
    if (CK) { int nke = (m0 + 128) >> 5; NK = (nke < NK) ? nke : NK; }

    const h16* gA = Ah + zA + (long)m0 * lda;
    const h16* gB = Bh + zB + (long)n0 * ldb;
    const int rgrp = tid >> 2;            // 0..63
    const int atom = tid & 3;

    float acc[4][NTI][4];
    #pragma unroll
    for (int a = 0; a < 4; a++)
        #pragma unroll
        for (int b = 0; b < NTI; b++)
            #pragma unroll
            for (int c = 0; c < 4; c++) acc[a][b][c] = 0.f;

    #define LOAD_STAGE(kt, slot) do {                                          \
        uint32_t st_ = sbase + (slot) * STG;                                   \
        _Pragma("unroll")                                                      \
        for (int i = 0; i < 2 + NB; i++) {                                     \
            const bool isA = (i < 2);                                          \
            const int lr = (isA ? i : (i - 2)) * 64 + rgrp;                    \
            const h16* g = (isA ? gA + (long)lr * lda : gB + (long)lr * ldb)   \
                           + ((kt) << 5) + (atom << 3);                        \
            CP_ASYNC16(st_ + (isA ? 0u : MAT_A) + (uint32_t)lr * 80u + (atom << 4), g); \
        }                                                                      \
        CP_COMMIT();                                                           \
    } while (0)

    LOAD_STAGE(0, 0);
    LOAD_STAGE(1, 1);

    for (int kt = 0; kt < NK; kt++) {
        CP_WAIT1();
        __syncthreads();
        if (kt + 2 < NK) { LOAD_STAGE(kt + 2, (kt + 2) % DEPTH); }
        else             { CP_COMMIT(); }

        uint32_t st = sbase + (kt % DEPTH) * STG;
        #pragma unroll
        for (int s = 0; s < 2; s++) {
            uint32_t a_h[4][4];
            #pragma unroll
            for (int mt = 0; mt < 4; mt++) {
                uint32_t ad = st + (uint32_t)(wm * 64 + mt * 16 + (lane & 15)) * 80u
                              + s * 32 + ((lane >> 4) << 4);
                LDSM_X4(a_h[mt], ad);
            }
            #pragma unroll
            for (int p = 0; p < NB; p++) {
                uint32_t b_h[4];
                uint32_t bd = st + MAT_A
                              + (uint32_t)(wn * (NT / 4) + p * 16 + ((lane >> 4) << 3) + (lane & 7)) * 80u
                              + s * 32 + (((lane >> 3) & 1) << 4);
                LDSM_X4(b_h, bd);
                #pragma unroll
                for (int q = 0; q < 2; q++) {
                    const int nt = p * 2 + q;
                    uint32_t bh0 = b_h[q * 2], bh1 = b_h[q * 2 + 1];
                    #pragma unroll
                    for (int mt = 0; mt < 4; mt++)
                        mma_f16(acc[mt][nt], a_h[mt], bh0, bh1);
                }
            }
        }
    }

    // ---- epilogue ----
    #pragma unroll
    for (int mt = 0; mt < 4; mt++) {
        #pragma unroll
        for (int nt = 0; nt < NTI; nt++) {
            int mbase = m0 + wm * 64 + mt * 16 + (lane >> 2);
            int n = n0 + wn * (NT / 4) + nt * 8 + (lane & 3) * 2;
            #pragma unroll
            for (int hf = 0; hf < 2; hf++) {
                int mm = mbase + hf * 8;
                float vx = acc[mt][nt][hf * 2 + 0];
                float vy = acc[mt][nt][hf * 2 + 1];
                long idx = zC + (long)mm * ldc + n;
                if (EPI >= 2) { vx += bias[n]; vy += bias[n + 1]; }
                if (EPI == 2) { vx = fmaxf(vx, 0.f); vy = fmaxf(vy, 0.f); }
                if (EPI == 1 || EPI == 3) {
                    float2 old = *(const float2*)(Cf + idx);
                    vx += old.x; vy += old.y;
                }
                if (F32OUT) {
                    float2 o; o.x = vx; o.y = vy;
                    *(float2*)(Cf + idx) = o;
                }
                if (F16OUT) {
                    *(__half2*)(Ch + idx) =
                        __halves2half2(__float2half_rn(vx), __float2half_rn(vy));
                }
            }
        }
    }
}

// ---------------- host ----------------
template<int EPI, bool F32O, bool F16O, bool CSKIP = false, bool CK = false, int NT = 256>
static void launch_mma(dim3 grid, const h16* Ah, const h16* Bh,
                       float* Cf, h16* Ch, const float* bias,
                       int K, int lda, int ldb, int ldc,
                       long bsA = 0, long bsB = 0, long bsC = 0) {
    constexpr int SMEM = DEPTH * (int)(MAT_A + (uint32_t)NT * 80u);
    cudaFuncSetAttribute(mma_gemm<EPI, F32O, F16O, CSKIP, CK, NT>,
                         cudaFuncAttributeMaxDynamicSharedMemorySize, SMEM);
    mma_gemm<EPI, F32O, F16O, CSKIP, CK, NT><<<grid, 256, SMEM>>>(
        Ah, Bh, Cf, Ch, bias, K, lda, ldb, ldc, bsA, bsB, bsC);
}

#define SYM(p, g) cudaGetSymbolAddress((void**)&p, g)

extern "C" void kernel_launch(void* const* d_in, const int* in_sizes, int n_in,
                              void* d_out, int out_size) {
    const int*   tokens    = (const int*)  d_in[0];
    const float* embedding = (const float*)d_in[1];
    const float* qkv_w     = (const float*)d_in[2];
    const float* o_w       = (const float*)d_in[3];
    const float* up_w      = (const float*)d_in[4];
    const float* up_b      = (const float*)d_in[5];
    const float* down_w    = (const float*)d_in[6];
    const float* down_b    = (const float*)d_in[7];
    const float* unemb_w   = (const float*)d_in[8];
    const float* unemb_b   = (const float*)d_in[9];
    float* logits = (float*)d_out;

    float *x, *sc;
    h16 *xh, *qh, *sh, *vTh, *oh, *hh;
    h16 *qkvT, *oT, *upT, *dnT, *unT;
    SYM(x, g_x); SYM(sc, g_scores);
    SYM(xh, g_xh);
    SYM(qh, g_qkvh);
    SYM(sh, g_sh);
    SYM(vTh, g_vTh);
    SYM(oh, g_oh);
    SYM(hh, g_hh);
    SYM(qkvT, g_qkvT); SYM(oT, g_oT); SYM(upT, g_upT); SYM(dnT, g_dnT); SYM(unT, g_unT);

    const float scale = 1.0f / sqrtf((float)KDIM);
    dim3 tb(32, 8);

    // weight transposes -> [N,K] single fp16
    transpose_f16<<<dim3(3 * KDIM / 32, HDIM / 32, LAYERS), tb>>>(
        qkv_w, qkvT, HDIM, 3 * KDIM, (long)HDIM * 3 * KDIM, (long)HDIM * 3 * KDIM);
    transpose_f16<<<dim3(HDIM / 32, KDIM / 32, LAYERS), tb>>>(
        o_w, oT, KDIM, HDIM, (long)KDIM * HDIM, (long)KDIM * HDIM);
    transpose_f16<<<dim3(IDIM / 32, HDIM / 32, LAYERS), tb>>>(
        up_w, upT, HDIM, IDIM, (long)HDIM * IDIM, (long)HDIM * IDIM);
    transpose_f16<<<dim3(HDIM / 32, IDIM / 32, LAYERS), tb>>>(
        down_w, dnT, IDIM, HDIM, (long)IDIM * HDIM, (long)IDIM * HDIM);
    transpose_f16<<<dim3(VOCAB / 32, HDIM / 32, 1), tb>>>(
        unemb_w, unT, HDIM, VOCAB, 0, 0);

    embed_f16<<<MTOK, 256>>>(tokens, embedding, x, xh);

    for (int l = 0; l < LAYERS; l++) {
        h16* wq = qkvT + (long)l * 3 * KDIM * HDIM;
        h16* wo = oT   + (long)l * HDIM * KDIM;
        h16* wu = upT  + (long)l * IDIM * HDIM;
        h16* wd = dnT  + (long)l * HDIM * IDIM;
        const float* bu = up_b   + (long)l * IDIM;
        const float* bd = down_b + (long)l * HDIM;

        // qkv = x @ Wqkv -> fp16 only
        launch_mma<0, false, true>(dim3(3 * KDIM / 256, MTOK / 128, 1),
            xh, wq, nullptr, qh, nullptr, HDIM, HDIM, HDIM, 3 * KDIM);

        // vT[b][k][t] = qh_V[b][t][k]  (fp16 -> fp16)
        transpose_h16<<<dim3(KDIM / 32, SEQ / 32, BATCH), tb>>>(
            qh + 2 * KDIM, vTh, SEQ, 3 * KDIM,
            (long)SEQ * 3 * KDIM, (long)KDIM * SEQ);

        // scores = Q @ K^T (causal block skip)
        launch_mma<0, true, false, true, false>(dim3(SEQ / 256, SEQ / 128, BATCH),
            qh, qh + KDIM, sc, nullptr, nullptr,
            KDIM, 3 * KDIM, 3 * KDIM, SEQ,
            (long)SEQ * 3 * KDIM, (long)SEQ * 3 * KDIM, (long)SEQ * SEQ);

        softmax_pair<<<BATCH * SEQ / 2, 256>>>(sc, sh, scale);

        // o = attn @ V (NT=128, K truncated, heavy tiles first)
        launch_mma<0, false, true, false, true, 128>(dim3(KDIM / 128, SEQ / 128, BATCH),
            sh, vTh, nullptr, oh, nullptr,
            SEQ, SEQ, SEQ, KDIM,
            (long)SEQ * SEQ, (long)KDIM * SEQ, (long)SEQ * KDIM);

        // x += o @ Wo -> fp32 + fp16
        launch_mma<1, true, true>(dim3(HDIM / 256, MTOK / 128, 1),
            oh, wo, x, xh, nullptr, KDIM, KDIM, KDIM, HDIM);

        // h = relu(x @ Wu + bu) -> fp16 only  (NT=128 for finer waves)
        launch_mma<2, false, true, false, false, 128>(dim3(IDIM / 128, MTOK / 128, 1),
            xh, wu, nullptr, hh, bu, HDIM, HDIM, HDIM, IDIM);

        // x += h @ Wd + bd -> fp32 + fp16
        launch_mma<3, true, true>(dim3(HDIM / 256, MTOK / 128, 1),
            hh, wd, x, xh, bd, IDIM, IDIM, IDIM, HDIM);
    }

    // logits = x @ Wun + b
    launch_mma<4, true, false>(dim3(VOCAB / 256, MTOK / 128, 1),
        xh, unT, logits, nullptr, unemb_b,
        HDIM, HDIM, HDIM, VOCAB);
}

// round 15
// speedup vs baseline: 6.2280x; 1.1037x over previous
#include <cuda_runtime.h>
#include <cuda_fp16.h>
#include <math.h>
#include <stdint.h>

#define LAYERS 8
#define HDIM   1024
#define KDIM   1024
#define IDIM   4096
#define VOCAB  32000
#define BATCH  2
#define SEQ    2048
#define MTOK   (BATCH * SEQ)

typedef __half h16;

// ---------------- scratch (device globals) ----------------
__device__ float g_x[(long)MTOK * HDIM];
__device__ float g_scores[(long)BATCH * SEQ * SEQ];
__device__ h16 g_xh[(long)MTOK * HDIM];
__device__ h16 g_qkvh[(long)MTOK * 3 * KDIM];
__device__ h16 g_sh[(long)BATCH * SEQ * SEQ];
__device__ h16 g_vTh[(long)BATCH * KDIM * SEQ];
__device__ h16 g_oh[(long)MTOK * KDIM];
__device__ h16 g_hh[(long)MTOK * IDIM];
// single-fp16 transposed weights [N,K]
__device__ h16 g_qkvT[(long)LAYERS * 3 * KDIM * HDIM];
__device__ h16 g_oT[(long)LAYERS * HDIM * KDIM];
__device__ h16 g_upT[(long)LAYERS * IDIM * HDIM];
__device__ h16 g_dnT[(long)LAYERS * HDIM * IDIM];
__device__ h16 g_unT[(long)VOCAB * HDIM];

// ---------------- helpers ----------------
__device__ __forceinline__ uint32_t smem_u32(const void* p) {
    uint32_t a;
    asm("{ .reg .u64 t; cvta.to.shared.u64 t, %1; cvt.u32.u64 %0, t; }" : "=r"(a) : "l"(p));
    return a;
}

#define CP_ASYNC16(dst, src) \
    asm volatile("cp.async.cg.shared.global [%0], [%1], 16;" :: "r"(dst), "l"(src) : "memory")
#define CP_COMMIT() asm volatile("cp.async.commit_group;" ::: "memory")
#define CP_WAIT1()  asm volatile("cp.async.wait_group 1;" ::: "memory")

#define LDSM_X4(r, a)                                                        \
    asm volatile("ldmatrix.sync.aligned.m8n8.x4.shared.b16 {%0,%1,%2,%3}, [%4];" \
        : "=r"((r)[0]), "=r"((r)[1]), "=r"((r)[2]), "=r"((r)[3]) : "r"(a))

__device__ __forceinline__ void mma_f16(float* c, const uint32_t* a,
                                        uint32_t b0, uint32_t b1) {
    asm volatile(
        "mma.sync.aligned.m16n8k16.row.col.f32.f16.f16.f32 "
        "{%0,%1,%2,%3}, {%4,%5,%6,%7}, {%8,%9}, {%0,%1,%2,%3};"
        : "+f"(c[0]), "+f"(c[1]), "+f"(c[2]), "+f"(c[3])
        : "r"(a[0]), "r"(a[1]), "r"(a[2]), "r"(a[3]), "r"(b0), "r"(b1));
}

// ---------------- embed (+fp16 copy) ----------------
__global__ void embed_f16(const int* __restrict__ tokens, const float* __restrict__ emb,
                          float* __restrict__ x, h16* __restrict__ xh) {
    int i = blockIdx.x;
    int tok = tokens[i];
    const float4* src = (const float4*)(emb + (long)tok * HDIM);
    float4* dst = (float4*)(x + (long)i * HDIM);
    for (int c = threadIdx.x; c < HDIM / 4; c += blockDim.x) {
        float4 v = src[c];
        dst[c] = v;
        long base = (long)i * HDIM + c * 4;
        *(__half2*)(xh + base)     = __halves2half2(__float2half_rn(v.x), __float2half_rn(v.y));
        *(__half2*)(xh + base + 2) = __halves2half2(__float2half_rn(v.z), __float2half_rn(v.w));
    }
}

// ---------------- transpose fp32 -> fp16 (batched) ----------------
__global__ void transpose_f16(const float* __restrict__ src, h16* __restrict__ dst,
                              int R, int lds, long sbatch, long dbatch) {
    __shared__ float t[32][33];
    src += (long)blockIdx.z * sbatch;
    dst += (long)blockIdx.z * dbatch;
    int c0 = blockIdx.x << 5, r0 = blockIdx.y << 5;
    int x = threadIdx.x, y = threadIdx.y;
    #pragma unroll
    for (int i = y; i < 32; i += 8)
        t[i][x] = src[(long)(r0 + i) * lds + c0 + x];
    __syncthreads();
    #pragma unroll
    for (int j = y; j < 32; j += 8)
        dst[(long)(c0 + j) * R + r0 + x] = __float2half_rn(t[x][j]);
}

// ---------------- transpose fp16 -> fp16 (batched, for V) ----------------
__global__ void transpose_h16(const h16* __restrict__ src, h16* __restrict__ dst,
                              int R, int lds, long sbatch, long dbatch) {
    __shared__ h16 t[32][33];
    src += (long)blockIdx.z * sbatch;
    dst += (long)blockIdx.z * dbatch;
    int c0 = blockIdx.x << 5, r0 = blockIdx.y << 5;
    int x = threadIdx.x, y = threadIdx.y;
    #pragma unroll
    for (int i = y; i < 32; i += 8)
        t[i][x] = src[(long)(r0 + i) * lds + c0 + x];
    __syncthreads();
    #pragma unroll
    for (int j = y; j < 32; j += 8)
        dst[(long)(c0 + j) * R + r0 + x] = t[x][j];
}

// ---------------- causal softmax -> fp16, balanced row pairs ---------------
__device__ __forceinline__ void softmax_row(float* __restrict__ sc,
                                            h16* __restrict__ sh,
                                            int b, int s, float scale,
                                            float* red) {
    float* p = sc + (long)(b * SEQ + s) * SEQ;
    h16* ph = sh + (long)(b * SEQ + s) * SEQ;
    int tid = threadIdx.x;

    float m = -INFINITY;
    for (int t = tid; t <= s; t += 256) m = fmaxf(m, p[t] * scale);
    red[tid] = m; __syncthreads();
    for (int o = 128; o > 0; o >>= 1) {
        if (tid < o) red[tid] = fmaxf(red[tid], red[tid + o]);
        __syncthreads();
    }
    m = red[0]; __syncthreads();

    float sum = 0.f;
    for (int t = tid; t <= s; t += 256) {
        float e = __expf(p[t] * scale - m);
        p[t] = e;
        sum += e;
    }
    red[tid] = sum; __syncthreads();
    for (int o = 128; o > 0; o >>= 1) {
        if (tid < o) red[tid] += red[tid + o];
        __syncthreads();
    }
    float inv = 1.f / red[0];
    __syncthreads();
    const h16 z = __float2half(0.f);
    for (int t = tid; t <= s; t += 256)
        ph[t] = __float2half_rn(p[t] * inv);
    for (int t = s + 1 + tid; t < SEQ; t += 256) ph[t] = z;
}

__global__ void softmax_pair(float* __restrict__ sc, h16* __restrict__ sh, float scale) {
    __shared__ float red[256];
    int pid = blockIdx.x;
    int b = pid / (SEQ / 2);
    int sp = pid % (SEQ / 2);
    softmax_row(sc, sh, b, sp, scale, red);
    __syncthreads();
    softmax_row(sc, sh, b, SEQ - 1 - sp, scale, red);
}

// ---------------- 1-pass HMMA GEMM: C = A @ B^T (both fp16) ----------------
// CTA tile 128 x NT x 32, 256 threads, 8 warps (2M x 4N), OCC CTAs/SM.
// EPI: 0 none, 1 +=Cf, 2 relu(+bias), 3 +bias+Cf, 4 +bias
// F32OUT: write Cf.  F16OUT: write Ch.
// CSKIP: skip blocks with n0 > m0+127.
// CK: truncate K loop at m0+128 AND flip blockIdx.y (heavy tiles first).
#define DEPTH  3
#define MAT_A  10240u                     // 128 rows * 80B

template<int EPI, bool F32OUT, bool F16OUT, bool CSKIP, bool CK, int NT, int OCC>
__global__ __launch_bounds__(256, OCC)
void mma_gemm(const h16* __restrict__ Ah, const h16* __restrict__ Bh,
              float* __restrict__ Cf, h16* __restrict__ Ch,
              const float* __restrict__ bias,
              int K, int lda, int ldb, int ldc,
              long bsA, long bsB, long bsC) {
    constexpr uint32_t MATB = (uint32_t)NT * 80u;
    constexpr uint32_t STG  = MAT_A + MATB;
    constexpr int NB  = NT / 64;
    constexpr int NTI = NT / 32;

    const int my = CK ? (gridDim.y - 1 - blockIdx.y) : blockIdx.y;
    const int m0 = my << 7;
    const int n0 = blockIdx.x * NT;
    if (CSKIP && n0 > m0 + 127) return;

    const long zA = (long)blockIdx.z * bsA;
    const long zB = (long)blockIdx.z * bsB;
    const long zC = (long)blockIdx.z * bsC;

    extern __shared__ char smem[];
    const uint32_t sbase = smem_u32(smem);
    const int tid = threadIdx.x;
    const int lane = tid & 31, wid = tid >> 5;
    const int wm = wid & 1, wn = wid >> 1;
    int NK = K >> 5;
    if (CK) { int nke = (m0 + 128) >> 5; NK = (nke < NK) ? nke : NK; }

    const h16* gA = Ah + zA + (long)m0 * lda;
    const h16* gB = Bh + zB + (long)n0 * ldb;
    const int rgrp = tid >> 2;
    const int atom = tid & 3;

    float acc[4][NTI][4];
    #pragma unroll
    for (int a = 0; a < 4; a++)
        #pragma unroll
        for (int b = 0; b < NTI; b++)
            #pragma unroll
            for (int c = 0; c < 4; c++) acc[a][b][c] = 0.f;

    #define LOAD_STAGE(kt, slot) do {                                          \
        uint32_t st_ = sbase + (slot) * STG;                                   \
        _Pragma("unroll")                                                      \
        for (int i = 0; i < 2 + NB; i++) {                                     \
            const bool isA = (i < 2);                                          \
            const int lr = (isA ? i : (i - 2)) * 64 + rgrp;                    \
            const h16* g = (isA ? gA + (long)lr * lda : gB + (long)lr * ldb)   \
                           + ((kt) << 5) + (atom << 3);                        \
            CP_ASYNC16(st_ + (isA ? 0u : MAT_A) + (uint32_t)lr * 80u + (atom << 4), g); \
        }                                                                      \
        CP_COMMIT();                                                           \
    } while (0)

    LOAD_STAGE(0, 0);
    LOAD_STAGE(1, 1);

    for (int kt = 0; kt < NK; kt++) {
        CP_WAIT1();
        __syncthreads();
        if (kt + 2 < NK) { LOAD_STAGE(kt + 2, (kt + 2) % DEPTH); }
        else             { CP_COMMIT(); }

        uint32_t st = sbase + (kt % DEPTH) * STG;
        #pragma unroll
        for (int s = 0; s < 2; s++) {
            uint32_t a_h[4][4];
            #pragma unroll
            for (int mt = 0; mt < 4; mt++) {
                uint32_t ad = st + (uint32_t)(wm * 64 + mt * 16 + (lane & 15)) * 80u
                              + s * 32 + ((lane >> 4) << 4);
                LDSM_X4(a_h[mt], ad);
            }
            #pragma unroll
            for (int p = 0; p < NB; p++) {
                uint32_t b_h[4];
                uint32_t bd = st + MAT_A
                              + (uint32_t)(wn * (NT / 4) + p * 16 + ((lane >> 4) << 3) + (lane & 7)) * 80u
                              + s * 32 + (((lane >> 3) & 1) << 4);
                LDSM_X4(b_h, bd);
                #pragma unroll
                for (int q = 0; q < 2; q++) {
                    const int nt = p * 2 + q;
                    uint32_t bh0 = b_h[q * 2], bh1 = b_h[q * 2 + 1];
                    #pragma unroll
                    for (int mt = 0; mt < 4; mt++)
                        mma_f16(acc[mt][nt], a_h[mt], bh0, bh1);
                }
            }
        }
    }

    // ---- epilogue ----
    #pragma unroll
    for (int mt = 0; mt < 4; mt++) {
        #pragma unroll
        for (int nt = 0; nt < NTI; nt++) {
            int mbase = m0 + wm * 64 + mt * 16 + (lane >> 2);
            int n = n0 + wn * (NT / 4) + nt * 8 + (lane & 3) * 2;
            #pragma unroll
            for (int hf = 0; hf < 2; hf++) {
                int mm = mbase + hf * 8;
                float vx = acc[mt][nt][hf * 2 + 0];
                float vy = acc[mt][nt][hf * 2 + 1];
                long idx = zC + (long)mm * ldc + n;
                if (EPI >= 2) { vx += bias[n]; vy += bias[n + 1]; }
                if (EPI == 2) { vx = fmaxf(vx, 0.f); vy = fmaxf(vy, 0.f); }
                if (EPI == 1 || EPI == 3) {
                    float2 old = *(const float2*)(Cf + idx);
                    vx += old.x; vy += old.y;
                }
                if (F32OUT) {
                    float2 o; o.x = vx; o.y = vy;
                    *(float2*)(Cf + idx) = o;
                }
                if (F16OUT) {
                    *(__half2*)(Ch + idx) =
                        __halves2half2(__float2half_rn(vx), __float2half_rn(vy));
                }
            }
        }
    }
}

// ---------------- host ----------------
template<int EPI, bool F32O, bool F16O, bool CSKIP = false, bool CK = false,
         int NT = 128, int OCC = 2>
static void launch_mma(dim3 grid, const h16* Ah, const h16* Bh,
                       float* Cf, h16* Ch, const float* bias,
                       int K, int lda, int ldb, int ldc,
                       long bsA = 0, long bsB = 0, long bsC = 0) {
    constexpr int SMEM = DEPTH * (int)(MAT_A + (uint32_t)NT * 80u);
    cudaFuncSetAttribute(mma_gemm<EPI, F32O, F16O, CSKIP, CK, NT, OCC>,
                         cudaFuncAttributeMaxDynamicSharedMemorySize, SMEM);
    mma_gemm<EPI, F32O, F16O, CSKIP, CK, NT, OCC><<<grid, 256, SMEM>>>(
        Ah, Bh, Cf, Ch, bias, K, lda, ldb, ldc, bsA, bsB, bsC);
}

#define SYM(p, g) cudaGetSymbolAddress((void**)&p, g)

extern "C" void kernel_launch(void* const* d_in, const int* in_sizes, int n_in,
                              void* d_out, int out_size) {
    const int*   tokens    = (const int*)  d_in[0];
    const float* embedding = (const float*)d_in[1];
    const float* qkv_w     = (const float*)d_in[2];
    const float* o_w       = (const float*)d_in[3];
    const float* up_w      = (const float*)d_in[4];
    const float* up_b      = (const float*)d_in[5];
    const float* down_w    = (const float*)d_in[6];
    const float* down_b    = (const float*)d_in[7];
    const float* unemb_w   = (const float*)d_in[8];
    const float* unemb_b   = (const float*)d_in[9];
    float* logits = (float*)d_out;

    float *x, *sc;
    h16 *xh, *qh, *sh, *vTh, *oh, *hh;
    h16 *qkvT, *oT, *upT, *dnT, *unT;
    SYM(x, g_x); SYM(sc, g_scores);
    SYM(xh, g_xh);
    SYM(qh, g_qkvh);
    SYM(sh, g_sh);
    SYM(vTh, g_vTh);
    SYM(oh, g_oh);
    SYM(hh, g_hh);
    SYM(qkvT, g_qkvT); SYM(oT, g_oT); SYM(upT, g_upT); SYM(dnT, g_dnT); SYM(unT, g_unT);

    const float scale = 1.0f / sqrtf((float)KDIM);
    dim3 tb(32, 8);

    // weight transposes -> [N,K] single fp16
    transpose_f16<<<dim3(3 * KDIM / 32, HDIM / 32, LAYERS), tb>>>(
        qkv_w, qkvT, HDIM, 3 * KDIM, (long)HDIM * 3 * KDIM, (long)HDIM * 3 * KDIM);
    transpose_f16<<<dim3(HDIM / 32, KDIM / 32, LAYERS), tb>>>(
        o_w, oT, KDIM, HDIM, (long)KDIM * HDIM, (long)KDIM * HDIM);
    transpose_f16<<<dim3(IDIM / 32, HDIM / 32, LAYERS), tb>>>(
        up_w, upT, HDIM, IDIM, (long)HDIM * IDIM, (long)HDIM * IDIM);
    transpose_f16<<<dim3(HDIM / 32, IDIM / 32, LAYERS), tb>>>(
        down_w, dnT, IDIM, HDIM, (long)IDIM * HDIM, (long)IDIM * HDIM);
    transpose_f16<<<dim3(VOCAB / 32, HDIM / 32, 1), tb>>>(
        unemb_w, unT, HDIM, VOCAB, 0, 0);

    embed_f16<<<MTOK, 256>>>(tokens, embedding, x, xh);

    for (int l = 0; l < LAYERS; l++) {
        h16* wq = qkvT + (long)l * 3 * KDIM * HDIM;
        h16* wo = oT   + (long)l * HDIM * KDIM;
        h16* wu = upT  + (long)l * IDIM * HDIM;
        h16* wd = dnT  + (long)l * HDIM * IDIM;
        const float* bu = up_b   + (long)l * IDIM;
        const float* bd = down_b + (long)l * HDIM;

        // qkv = x @ Wqkv -> fp16 only
        launch_mma<0, false, true>(dim3(3 * KDIM / 128, MTOK / 128, 1),
            xh, wq, nullptr, qh, nullptr, HDIM, HDIM, HDIM, 3 * KDIM);

        // vT[b][k][t] = qh_V[b][t][k]  (fp16 -> fp16)
        transpose_h16<<<dim3(KDIM / 32, SEQ / 32, BATCH), tb>>>(
            qh + 2 * KDIM, vTh, SEQ, 3 * KDIM,
            (long)SEQ * 3 * KDIM, (long)KDIM * SEQ);

        // scores = Q @ K^T (causal block skip)
        launch_mma<0, true, false, true, false>(dim3(SEQ / 128, SEQ / 128, BATCH),
            qh, qh + KDIM, sc, nullptr, nullptr,
            KDIM, 3 * KDIM, 3 * KDIM, SEQ,
            (long)SEQ * 3 * KDIM, (long)SEQ * 3 * KDIM, (long)SEQ * SEQ);

        softmax_pair<<<BATCH * SEQ / 2, 256>>>(sc, sh, scale);

        // o = attn @ V (K truncated, heavy tiles first)
        launch_mma<0, false, true, false, true>(dim3(KDIM / 128, SEQ / 128, BATCH),
            sh, vTh, nullptr, oh, nullptr,
            SEQ, SEQ, SEQ, KDIM,
            (long)SEQ * SEQ, (long)KDIM * SEQ, (long)SEQ * KDIM);

        // x += o @ Wo -> fp32 + fp16
        launch_mma<1, true, true>(dim3(HDIM / 128, MTOK / 128, 1),
            oh, wo, x, xh, nullptr, KDIM, KDIM, KDIM, HDIM);

        // h = relu(x @ Wu + bu) -> fp16 only
        launch_mma<2, false, true>(dim3(IDIM / 128, MTOK / 128, 1),
            xh, wu, nullptr, hh, bu, HDIM, HDIM, HDIM, IDIM);

        // x += h @ Wd + bd -> fp32 + fp16
        launch_mma<3, true, true>(dim3(HDIM / 128, MTOK / 128, 1),
            hh, wd, x, xh, bd, IDIM, IDIM, IDIM, HDIM);
    }

    // logits = x @ Wun + b
    launch_mma<4, true, false>(dim3(VOCAB / 128, MTOK / 128, 1),
        xh, unT, logits, nullptr, unemb_b,
        HDIM, HDIM, HDIM, VOCAB);
}

// round 16
// speedup vs baseline: 6.2315x; 1.0006x over previous
#include <cuda_runtime.h>
#include <cuda_fp16.h>
#include <math.h>
#include <stdint.h>

#define LAYERS 8
#define HDIM   1024
#define KDIM   1024
#define IDIM   4096
#define VOCAB  32000
#define BATCH  2
#define SEQ    2048
#define MTOK   (BATCH * SEQ)

typedef __half h16;

// ---------------- scratch (device globals) ----------------
__device__ float g_x[(long)MTOK * HDIM];
__device__ float g_scores[(long)BATCH * SEQ * SEQ];
__device__ h16 g_xh[(long)MTOK * HDIM];
__device__ h16 g_qkvh[(long)MTOK * 3 * KDIM];
__device__ h16 g_sh[(long)BATCH * SEQ * SEQ];
__device__ h16 g_vTh[(long)BATCH * KDIM * SEQ];
__device__ h16 g_oh[(long)MTOK * KDIM];
__device__ h16 g_hh[(long)MTOK * IDIM];
// single-fp16 transposed weights [N,K]
__device__ h16 g_qkvT[(long)LAYERS * 3 * KDIM * HDIM];
__device__ h16 g_oT[(long)LAYERS * HDIM * KDIM];
__device__ h16 g_upT[(long)LAYERS * IDIM * HDIM];
__device__ h16 g_dnT[(long)LAYERS * HDIM * IDIM];
__device__ h16 g_unT[(long)VOCAB * HDIM];

// ---------------- helpers ----------------
__device__ __forceinline__ uint32_t smem_u32(const void* p) {
    uint32_t a;
    asm("{ .reg .u64 t; cvta.to.shared.u64 t, %1; cvt.u32.u64 %0, t; }" : "=r"(a) : "l"(p));
    return a;
}

#define CP_ASYNC16(dst, src) \
    asm volatile("cp.async.cg.shared.global [%0], [%1], 16;" :: "r"(dst), "l"(src) : "memory")
#define CP_COMMIT() asm volatile("cp.async.commit_group;" ::: "memory")
#define CP_WAIT2()  asm volatile("cp.async.wait_group 2;" ::: "memory")

#define LDSM_X4(r, a)                                                        \
    asm volatile("ldmatrix.sync.aligned.m8n8.x4.shared.b16 {%0,%1,%2,%3}, [%4];" \
        : "=r"((r)[0]), "=r"((r)[1]), "=r"((r)[2]), "=r"((r)[3]) : "r"(a))

__device__ __forceinline__ void mma_f16(float* c, const uint32_t* a,
                                        uint32_t b0, uint32_t b1) {
    asm volatile(
        "mma.sync.aligned.m16n8k16.row.col.f32.f16.f16.f32 "
        "{%0,%1,%2,%3}, {%4,%5,%6,%7}, {%8,%9}, {%0,%1,%2,%3};"
        : "+f"(c[0]), "+f"(c[1]), "+f"(c[2]), "+f"(c[3])
        : "r"(a[0]), "r"(a[1]), "r"(a[2]), "r"(a[3]), "r"(b0), "r"(b1));
}

// ---------------- embed (+fp16 copy) ----------------
__global__ void embed_f16(const int* __restrict__ tokens, const float* __restrict__ emb,
                          float* __restrict__ x, h16* __restrict__ xh) {
    int i = blockIdx.x;
    int tok = tokens[i];
    const float4* src = (const float4*)(emb + (long)tok * HDIM);
    float4* dst = (float4*)(x + (long)i * HDIM);
    for (int c = threadIdx.x; c < HDIM / 4; c += blockDim.x) {
        float4 v = src[c];
        dst[c] = v;
        long base = (long)i * HDIM + c * 4;
        *(__half2*)(xh + base)     = __halves2half2(__float2half_rn(v.x), __float2half_rn(v.y));
        *(__half2*)(xh + base + 2) = __halves2half2(__float2half_rn(v.z), __float2half_rn(v.w));
    }
}

// ---------------- transpose fp32 -> fp16 (batched) ----------------
__global__ void transpose_f16(const float* __restrict__ src, h16* __restrict__ dst,
                              int R, int lds, long sbatch, long dbatch) {
    __shared__ float t[32][33];
    src += (long)blockIdx.z * sbatch;
    dst += (long)blockIdx.z * dbatch;
    int c0 = blockIdx.x << 5, r0 = blockIdx.y << 5;
    int x = threadIdx.x, y = threadIdx.y;
    #pragma unroll
    for (int i = y; i < 32; i += 8)
        t[i][x] = src[(long)(r0 + i) * lds + c0 + x];
    __syncthreads();
    #pragma unroll
    for (int j = y; j < 32; j += 8)
        dst[(long)(c0 + j) * R + r0 + x] = __float2half_rn(t[x][j]);
}

// ---------------- transpose fp16 -> fp16 (batched, for V) ----------------
__global__ void transpose_h16(const h16* __restrict__ src, h16* __restrict__ dst,
                              int R, int lds, long sbatch, long dbatch) {
    __shared__ h16 t[32][33];
    src += (long)blockIdx.z * sbatch;
    dst += (long)blockIdx.z * dbatch;
    int c0 = blockIdx.x << 5, r0 = blockIdx.y << 5;
    int x = threadIdx.x, y = threadIdx.y;
    #pragma unroll
    for (int i = y; i < 32; i += 8)
        t[i][x] = src[(long)(r0 + i) * lds + c0 + x];
    __syncthreads();
    #pragma unroll
    for (int j = y; j < 32; j += 8)
        dst[(long)(c0 + j) * R + r0 + x] = t[x][j];
}

// ---------------- causal softmax -> fp16, register-cached, row pairs -------
__device__ __forceinline__ void softmax_row(const float* __restrict__ sc,
                                            h16* __restrict__ sh,
                                            int b, int s, float scale,
                                            float* red) {
    const float* p = sc + (long)(b * SEQ + s) * SEQ;
    h16* ph = sh + (long)(b * SEQ + s) * SEQ;
    int tid = threadIdx.x;

    float v[8];
    #pragma unroll
    for (int i = 0; i < 8; i++) {
        int t = tid + i * 256;
        v[i] = (t <= s) ? p[t] * scale : -INFINITY;
    }

    float m = -INFINITY;
    #pragma unroll
    for (int i = 0; i < 8; i++) m = fmaxf(m, v[i]);
    red[tid] = m; __syncthreads();
    for (int o = 128; o > 0; o >>= 1) {
        if (tid < o) red[tid] = fmaxf(red[tid], red[tid + o]);
        __syncthreads();
    }
    m = red[0]; __syncthreads();

    float sum = 0.f;
    #pragma unroll
    for (int i = 0; i < 8; i++) {
        int t = tid + i * 256;
        if (t <= s) {
            v[i] = __expf(v[i] - m);
            sum += v[i];
        }
    }
    red[tid] = sum; __syncthreads();
    for (int o = 128; o > 0; o >>= 1) {
        if (tid < o) red[tid] += red[tid + o];
        __syncthreads();
    }
    float inv = 1.f / red[0];
    __syncthreads();

    const h16 z = __float2half(0.f);
    #pragma unroll
    for (int i = 0; i < 8; i++) {
        int t = tid + i * 256;
        ph[t] = (t <= s) ? __float2half_rn(v[i] * inv) : z;
    }
}

__global__ void softmax_pair(const float* __restrict__ sc, h16* __restrict__ sh,
                             float scale) {
    __shared__ float red[256];
    int pid = blockIdx.x;
    int b = pid / (SEQ / 2);
    int sp = pid % (SEQ / 2);
    softmax_row(sc, sh, b, sp, scale, red);
    __syncthreads();
    softmax_row(sc, sh, b, SEQ - 1 - sp, scale, red);
}

// ---------------- 1-pass HMMA GEMM: C = A @ B^T (both fp16) ----------------
// CTA tile 128 x NT x 32, 256 threads, 8 warps (2M x 4N), OCC CTAs/SM.
// DEPTH=4 cp.async ring, two stages in flight.
// EPI: 0 none, 1 +=Cf, 2 relu(+bias), 3 +bias+Cf, 4 +bias
// F32OUT: write Cf.  F16OUT: write Ch.
// CSKIP: skip blocks with n0 > m0+127.
// CK: truncate K loop at m0+128 AND flip blockIdx.y (heavy tiles first).
#define DEPTH  4
#define MAT_A  10240u                     // 128 rows * 80B

template<int EPI, bool F32OUT, bool F16OUT, bool CSKIP, bool CK, int NT, int OCC>
__global__ __launch_bounds__(256, OCC)
void mma_gemm(const h16* __restrict__ Ah, const h16* __restrict__ Bh,
              float* __restrict__ Cf, h16* __restrict__ Ch,
              const float* __restrict__ bias,
              int K, int lda, int ldb, int ldc,
              long bsA, long bsB, long bsC) {
    constexpr uint32_t MATB = (uint32_t)NT * 80u;
    constexpr uint32_t STG  = MAT_A + MATB;
    constexpr int NB  = NT / 64;
    constexpr int NTI = NT / 32;

    const int my = CK ? (gridDim.y - 1 - blockIdx.y) : blockIdx.y;
    const int m0 = my << 7;
    const int n0 = blockIdx.x * NT;
    if (CSKIP && n0 > m0 + 127) return;

    const long zA = (long)blockIdx.z * bsA;
    const long zB = (long)blockIdx.z * bsB;
    const long zC = (long)blockIdx.z * bsC;

    extern __shared__ char smem[];
    const uint32_t sbase = smem_u32(smem);
    const int tid = threadIdx.x;
    const int lane = tid & 31, wid = tid >> 5;
    const int wm = wid & 1, wn = wid >> 1;
    int NK = K >> 5;
    if (CK) { int nke = (m0 + 128) >> 5; NK = (nke < NK) ? nke : NK; }

    const h16* gA = Ah + zA + (long)m0 * lda;
    const h16* gB = Bh + zB + (long)n0 * ldb;
    const int rgrp = tid >> 2;
    const int atom = tid & 3;

    float acc[4][NTI][4];
    #pragma unroll
    for (int a = 0; a < 4; a++)
        #pragma unroll
        for (int b = 0; b < NTI; b++)
            #pragma unroll
            for (int c = 0; c < 4; c++) acc[a][b][c] = 0.f;

    #define LOAD_STAGE(kt, slot) do {                                          \
        uint32_t st_ = sbase + (slot) * STG;                                   \
        _Pragma("unroll")                                                      \
        for (int i = 0; i < 2 + NB; i++) {                                     \
            const bool isA = (i < 2);                                          \
            const int lr = (isA ? i : (i - 2)) * 64 + rgrp;                    \
            const h16* g = (isA ? gA + (long)lr * lda : gB + (long)lr * ldb)   \
                           + ((kt) << 5) + (atom << 3);                        \
            CP_ASYNC16(st_ + (isA ? 0u : MAT_A) + (uint32_t)lr * 80u + (atom << 4), g); \
        }                                                                      \
        CP_COMMIT();                                                           \
    } while (0)

    LOAD_STAGE(0, 0);
    if (NK > 1) LOAD_STAGE(1, 1); else CP_COMMIT();
    if (NK > 2) LOAD_STAGE(2, 2); else CP_COMMIT();

    for (int kt = 0; kt < NK; kt++) {
        CP_WAIT2();
        __syncthreads();
        if (kt + 3 < NK) { LOAD_STAGE(kt + 3, (kt + 3) & 3); }
        else             { CP_COMMIT(); }

        uint32_t st = sbase + (kt & 3) * STG;
        #pragma unroll
        for (int s = 0; s < 2; s++) {
            uint32_t a_h[4][4];
            #pragma unroll
            for (int mt = 0; mt < 4; mt++) {
                uint32_t ad = st + (uint32_t)(wm * 64 + mt * 16 + (lane & 15)) * 80u
                              + s * 32 + ((lane >> 4) << 4);
                LDSM_X4(a_h[mt], ad);
            }
            #pragma unroll
            for (int p = 0; p < NB; p++) {
                uint32_t b_h[4];
                uint32_t bd = st + MAT_A
                              + (uint32_t)(wn * (NT / 4) + p * 16 + ((lane >> 4) << 3) + (lane & 7)) * 80u
                              + s * 32 + (((lane >> 3) & 1) << 4);
                LDSM_X4(b_h, bd);
                #pragma unroll
                for (int q = 0; q < 2; q++) {
                    const int nt = p * 2 + q;
                    uint32_t bh0 = b_h[q * 2], bh1 = b_h[q * 2 + 1];
                    #pragma unroll
                    for (int mt = 0; mt < 4; mt++)
                        mma_f16(acc[mt][nt], a_h[mt], bh0, bh1);
                }
            }
        }
    }

    // ---- epilogue ----
    #pragma unroll
    for (int mt = 0; mt < 4; mt++) {
        #pragma unroll
        for (int nt = 0; nt < NTI; nt++) {
            int mbase = m0 + wm * 64 + mt * 16 + (lane >> 2);
            int n = n0 + wn * (NT / 4) + nt * 8 + (lane & 3) * 2;
            #pragma unroll
            for (int hf = 0; hf < 2; hf++) {
                int mm = mbase + hf * 8;
                float vx = acc[mt][nt][hf * 2 + 0];
                float vy = acc[mt][nt][hf * 2 + 1];
                long idx = zC + (long)mm * ldc + n;
                if (EPI >= 2) { vx += bias[n]; vy += bias[n + 1]; }
                if (EPI == 2) { vx = fmaxf(vx, 0.f); vy = fmaxf(vy, 0.f); }
                if (EPI == 1 || EPI == 3) {
                    float2 old = *(const float2*)(Cf + idx);
                    vx += old.x; vy += old.y;
                }
                if (F32OUT) {
                    float2 o; o.x = vx; o.y = vy;
                    *(float2*)(Cf + idx) = o;
                }
                if (F16OUT) {
                    *(__half2*)(Ch + idx) =
                        __halves2half2(__float2half_rn(vx), __float2half_rn(vy));
                }
            }
        }
    }
}

// ---------------- host ----------------
template<int EPI, bool F32O, bool F16O, bool CSKIP = false, bool CK = false,
         int NT = 128, int OCC = 2>
static void launch_mma(dim3 grid, const h16* Ah, const h16* Bh,
                       float* Cf, h16* Ch, const float* bias,
                       int K, int lda, int ldb, int ldc,
                       long bsA = 0, long bsB = 0, long bsC = 0) {
    constexpr int SMEM = DEPTH * (int)(MAT_A + (uint32_t)NT * 80u);
    cudaFuncSetAttribute(mma_gemm<EPI, F32O, F16O, CSKIP, CK, NT, OCC>,
                         cudaFuncAttributeMaxDynamicSharedMemorySize, SMEM);
    mma_gemm<EPI, F32O, F16O, CSKIP, CK, NT, OCC><<<grid, 256, SMEM>>>(
        Ah, Bh, Cf, Ch, bias, K, lda, ldb, ldc, bsA, bsB, bsC);
}

#define SYM(p, g) cudaGetSymbolAddress((void**)&p, g)

extern "C" void kernel_launch(void* const* d_in, const int* in_sizes, int n_in,
                              void* d_out, int out_size) {
    const int*   tokens    = (const int*)  d_in[0];
    const float* embedding = (const float*)d_in[1];
    const float* qkv_w     = (const float*)d_in[2];
    const float* o_w       = (const float*)d_in[3];
    const float* up_w      = (const float*)d_in[4];
    const float* up_b      = (const float*)d_in[5];
    const float* down_w    = (const float*)d_in[6];
    const float* down_b    = (const float*)d_in[7];
    const float* unemb_w   = (const float*)d_in[8];
    const float* unemb_b   = (const float*)d_in[9];
    float* logits = (float*)d_out;

    float *x, *sc;
    h16 *xh, *qh, *sh, *vTh, *oh, *hh;
    h16 *qkvT, *oT, *upT, *dnT, *unT;
    SYM(x, g_x); SYM(sc, g_scores);
    SYM(xh, g_xh);
    SYM(qh, g_qkvh);
    SYM(sh, g_sh);
    SYM(vTh, g_vTh);
    SYM(oh, g_oh);
    SYM(hh, g_hh);
    SYM(qkvT, g_qkvT); SYM(oT, g_oT); SYM(upT, g_upT); SYM(dnT, g_dnT); SYM(unT, g_unT);

    const float scale = 1.0f / sqrtf((float)KDIM);
    dim3 tb(32, 8);

    // weight transposes -> [N,K] single fp16
    transpose_f16<<<dim3(3 * KDIM / 32, HDIM / 32, LAYERS), tb>>>(
        qkv_w, qkvT, HDIM, 3 * KDIM, (long)HDIM * 3 * KDIM, (long)HDIM * 3 * KDIM);
    transpose_f16<<<dim3(HDIM / 32, KDIM / 32, LAYERS), tb>>>(
        o_w, oT, KDIM, HDIM, (long)KDIM * HDIM, (long)KDIM * HDIM);
    transpose_f16<<<dim3(IDIM / 32, HDIM / 32, LAYERS), tb>>>(
        up_w, upT, HDIM, IDIM, (long)HDIM * IDIM, (long)HDIM * IDIM);
    transpose_f16<<<dim3(HDIM / 32, IDIM / 32, LAYERS), tb>>>(
        down_w, dnT, IDIM, HDIM, (long)IDIM * HDIM, (long)IDIM * HDIM);
    transpose_f16<<<dim3(VOCAB / 32, HDIM / 32, 1), tb>>>(
        unemb_w, unT, HDIM, VOCAB, 0, 0);

    embed_f16<<<MTOK, 256>>>(tokens, embedding, x, xh);

    for (int l = 0; l < LAYERS; l++) {
        h16* wq = qkvT + (long)l * 3 * KDIM * HDIM;
        h16* wo = oT   + (long)l * HDIM * KDIM;
        h16* wu = upT  + (long)l * IDIM * HDIM;
        h16* wd = dnT  + (long)l * HDIM * IDIM;
        const float* bu = up_b   + (long)l * IDIM;
        const float* bd = down_b + (long)l * HDIM;

        // qkv = x @ Wqkv -> fp16 only
        launch_mma<0, false, true>(dim3(3 * KDIM / 128, MTOK / 128, 1),
            xh, wq, nullptr, qh, nullptr, HDIM, HDIM, HDIM, 3 * KDIM);

        // vT[b][k][t] = qh_V[b][t][k]  (fp16 -> fp16)
        transpose_h16<<<dim3(KDIM / 32, SEQ / 32, BATCH), tb>>>(
            qh + 2 * KDIM, vTh, SEQ, 3 * KDIM,
            (long)SEQ * 3 * KDIM, (long)KDIM * SEQ);

        // scores = Q @ K^T (causal block skip)
        launch_mma<0, true, false, true, false>(dim3(SEQ / 128, SEQ / 128, BATCH),
            qh, qh + KDIM, sc, nullptr, nullptr,
            KDIM, 3 * KDIM, 3 * KDIM, SEQ,
            (long)SEQ * 3 * KDIM, (long)SEQ * 3 * KDIM, (long)SEQ * SEQ);

        softmax_pair<<<BATCH * SEQ / 2, 256>>>(sc, sh, scale);

        // o = attn @ V (K truncated, heavy tiles first)
        launch_mma<0, false, true, false, true>(dim3(KDIM / 128, SEQ / 128, BATCH),
            sh, vTh, nullptr, oh, nullptr,
            SEQ, SEQ, SEQ, KDIM,
            (long)SEQ * SEQ, (long)KDIM * SEQ, (long)SEQ * KDIM);

        // x += o @ Wo -> fp32 + fp16
        launch_mma<1, true, true>(dim3(HDIM / 128, MTOK / 128, 1),
            oh, wo, x, xh, nullptr, KDIM, KDIM, KDIM, HDIM);

        // h = relu(x @ Wu + bu) -> fp16 only
        launch_mma<2, false, true>(dim3(IDIM / 128, MTOK / 128, 1),
            xh, wu, nullptr, hh, bu, HDIM, HDIM, HDIM, IDIM);

        // x += h @ Wd + bd -> fp32 + fp16
        launch_mma<3, true, true>(dim3(HDIM / 128, MTOK / 128, 1),
            hh, wd, x, xh, bd, IDIM, IDIM, IDIM, HDIM);
    }

    // logits = x @ Wun + b
    launch_mma<4, true, false>(dim3(VOCAB / 128, MTOK / 128, 1),
        xh, unT, logits, nullptr, unemb_b,
        HDIM, HDIM, HDIM, VOCAB);
}